// round 13
// baseline (speedup 1.0000x reference)
#include <cuda_runtime.h>
#include <cuda_fp16.h>
#include <math_constants.h>
#include <cstdint>

// ---------------------------------------------------------------------------
// Problem constants
// ---------------------------------------------------------------------------
#define BATCH     8192
#define NCODE     8192
#define PRED_ELEMS ((size_t)BATCH * 4096)
#define LOSS_OFF   PRED_ELEMS
#define IDX_OFF    (PRED_ELEMS + 1)

// Exact power-of-2 scales keeping fp16 'lo' residuals in normal range
#define WSCALE 1024.0f
#define ASCALE 32.0f
#define UNSCALE (1.0f / (WSCALE * ASCALE))

// ---------------------------------------------------------------------------
// Helpers
// ---------------------------------------------------------------------------
__device__ __forceinline__ uint32_t smem_u32(const void* p) {
    uint32_t a;
    asm("{ .reg .u64 t; cvta.to.shared.u64 t, %1; cvt.u32.u64 %0, t; }"
        : "=r"(a) : "l"(p));
    return a;
}
__device__ __forceinline__ void cp_async16(uint32_t dst, const void* src) {
    asm volatile("cp.async.cg.shared.global [%0], [%1], 16;" :: "r"(dst), "l"(src) : "memory");
}
#define CP_COMMIT() asm volatile("cp.async.commit_group;" ::: "memory")
#define CP_WAIT2()  asm volatile("cp.async.wait_group 2;" ::: "memory")

__device__ __forceinline__ void ldsm4(uint32_t* r, uint32_t addr) {
    asm volatile("ldmatrix.sync.aligned.m8n8.x4.shared.b16 {%0,%1,%2,%3}, [%4];"
                 : "=r"(r[0]), "=r"(r[1]), "=r"(r[2]), "=r"(r[3]) : "r"(addr));
}
__device__ __forceinline__ void mma16816(float* c, const uint32_t* a, const uint32_t* b) {
    asm volatile("mma.sync.aligned.m16n8k16.row.col.f32.f16.f16.f32 "
                 "{%0,%1,%2,%3}, {%4,%5,%6,%7}, {%8,%9}, {%0,%1,%2,%3};"
                 : "+f"(c[0]), "+f"(c[1]), "+f"(c[2]), "+f"(c[3])
                 : "r"(a[0]), "r"(a[1]), "r"(a[2]), "r"(a[3]), "r"(b[0]), "r"(b[1]));
}

// Packed dual-fp32 FMA (Blackwell f32x2; each half is an exact fp32 fma.rn —
// accumulation chains remain bit-identical to scalar FFMA).
__device__ __forceinline__ void fma_f32x2(unsigned long long& c,
                                          unsigned long long a,
                                          unsigned long long b) {
    asm("fma.rn.f32x2 %0, %1, %2, %0;" : "+l"(c) : "l"(a), "l"(b));
}
__device__ __forceinline__ unsigned long long dup_f32x2(float x) {
    unsigned long long d;
    asm("mov.b64 %0, {%1, %1};" : "=l"(d) : "f"(x));
    return d;
}
__device__ __forceinline__ void unpack_f32x2(float& lo, float& hi,
                                             unsigned long long v) {
    asm("mov.b64 {%0, %1}, %2;" : "=f"(lo), "=f"(hi) : "l"(v));
}

// ---------------------------------------------------------------------------
// Scratch buffers
// ---------------------------------------------------------------------------
__device__ float g_bufB[(size_t)BATCH * 2048];   // 64 MB
__device__ float g_bufC[(size_t)BATCH * 1024];   // 32 MB
__device__ float g_bufD[(size_t)BATCH * 512];    // 16 MB
__device__ float g_bufZ[(size_t)BATCH * 512];    // 16 MB
__device__ __half g_zsth[4194304], g_zstl[4194304];
__device__ __half g_g1h[8388608],  g_g1l[8388608];
__device__ __half g_g2h[16777216], g_g2l[16777216];
__device__ __half g_g3h[33554432], g_g3l[33554432];
__device__ __half g_v1h[524288],   g_v1l[524288];
__device__ __half g_v2h[2097152],  g_v2l[2097152];
__device__ __half g_v3h[8388608],  g_v3l[8388608];
__device__ __half g_v4h[16777216], g_v4l[16777216];
__device__ float g_znorm[BATCH];
__device__ float g_enorm[NCODE];
__device__ float g_cand_d[64 * BATCH];
__device__ int   g_cand_i[64 * BATCH];
__device__ int   g_idx[BATCH];
__device__ float g_lossPart[BATCH];

// ---------------------------------------------------------------------------
// fp32 SGEMM, f32x2 mainloop: C[M,N] = act(A[M,K] @ W[N,K]^T + bias[N])
// Same tiling/order as R3; per-element fma chain identical (k ascending),
// so z / indices / loss are bit-identical to the passing R3/R12 runs.
// ---------------------------------------------------------------------------
template <bool RELU>
__global__ __launch_bounds__(256)
void sgemm_bias(const float* __restrict__ A, const float* __restrict__ W,
                const float* __restrict__ bias, float* __restrict__ C,
                int M, int N, int K)
{
    __shared__ float As[16][132];
    __shared__ float Ws[16][132];

    const int tid  = threadIdx.x;
    const int brow = blockIdx.y * 128;
    const int bcol = blockIdx.x * 128;

    const int lr = tid >> 2;          // 0..63
    const int lk = (tid & 3) << 2;    // 0,4,8,12
    const float* Ap = A + (size_t)(brow + lr) * K + lk;
    const float* Wp = W + (size_t)(bcol + lr) * K + lk;

    const int trow = (tid >> 4) << 3; // 0..120
    const int tcol = (tid & 15) << 3;

    unsigned long long acc2[8][4];    // packed column pairs (j, j+1)
#pragma unroll
    for (int i = 0; i < 8; i++)
#pragma unroll
        for (int j = 0; j < 4; j++) acc2[i][j] = 0ull;

    for (int k0 = 0; k0 < K; k0 += 16) {
#pragma unroll
        for (int h = 0; h < 2; h++) {
            float4 a = *(const float4*)(Ap + (size_t)(h * 64) * K + k0);
            float4 w = *(const float4*)(Wp + (size_t)(h * 64) * K + k0);
            int r = lr + h * 64;
            As[lk + 0][r] = a.x; As[lk + 1][r] = a.y;
            As[lk + 2][r] = a.z; As[lk + 3][r] = a.w;
            Ws[lk + 0][r] = w.x; Ws[lk + 1][r] = w.y;
            Ws[lk + 2][r] = w.z; Ws[lk + 3][r] = w.w;
        }
        __syncthreads();
#pragma unroll
        for (int kk = 0; kk < 16; kk++) {
            float ra[8];
            unsigned long long rb2[4];
            *(float4*)(ra)     = *(const float4*)&As[kk][trow];
            *(float4*)(ra + 4) = *(const float4*)&As[kk][trow + 4];
            // column pairs are adjacent in Ws — reinterpret LDS.128 as 2x b64
            *(ulonglong2*)(rb2)     = *(const ulonglong2*)&Ws[kk][tcol];
            *(ulonglong2*)(rb2 + 2) = *(const ulonglong2*)&Ws[kk][tcol + 4];
#pragma unroll
            for (int i = 0; i < 8; i++) {
                unsigned long long ap = dup_f32x2(ra[i]);
#pragma unroll
                for (int j = 0; j < 4; j++)
                    fma_f32x2(acc2[i][j], ap, rb2[j]);
            }
        }
        __syncthreads();
    }

#pragma unroll
    for (int i = 0; i < 8; i++) {
        int row = brow + trow + i;
        float accv[8];
#pragma unroll
        for (int j = 0; j < 4; j++)
            unpack_f32x2(accv[2 * j], accv[2 * j + 1], acc2[i][j]);
#pragma unroll
        for (int j = 0; j < 8; j += 4) {
            int col = bcol + tcol + j;
            float4 bv = *(const float4*)&bias[col];
            float4 v;
            v.x = accv[j + 0] + bv.x;
            v.y = accv[j + 1] + bv.y;
            v.z = accv[j + 2] + bv.z;
            v.w = accv[j + 3] + bv.w;
            if (RELU) {
                v.x = fmaxf(v.x, 0.0f); v.y = fmaxf(v.y, 0.0f);
                v.z = fmaxf(v.z, 0.0f); v.w = fmaxf(v.w, 0.0f);
            }
            *(float4*)&C[(size_t)row * N + col] = v;
        }
    }
}

// ---------------------------------------------------------------------------
// fp32 -> (fp16 hi, fp16 lo) split of (x * scale)
// ---------------------------------------------------------------------------
__global__ void split4(const float4* __restrict__ src, __half2* __restrict__ h,
                       __half2* __restrict__ l, int n4, float scale)
{
    int i = blockIdx.x * blockDim.x + threadIdx.x;
    if (i >= n4) return;
    float4 x = src[i];
    x.x *= scale; x.y *= scale; x.z *= scale; x.w *= scale;
    __half2 h0 = __floats2half2_rn(x.x, x.y);
    __half2 h1 = __floats2half2_rn(x.z, x.w);
    __half2 l0 = __floats2half2_rn(x.x - __low2float(h0), x.y - __high2float(h0));
    __half2 l1 = __floats2half2_rn(x.z - __low2float(h1), x.w - __high2float(h1));
    h[2 * i] = h0; h[2 * i + 1] = h1;
    l[2 * i] = l0; l[2 * i + 1] = l1;
}

// ---------------------------------------------------------------------------
// HMMA split-fp16 GEMM (decoder; unchanged from R12 passing run)
// ---------------------------------------------------------------------------
#define TM 128
#define TN 128
#define KC 32
#define ROWPAD 40
#define PLANE (TM * ROWPAD)
#define STAGE_HALFS (4 * PLANE)
#define GEMM_SMEM (3 * STAGE_HALFS * 2)

template <int RELU, int WS, int WF>
__global__ void __launch_bounds__(256)
tc_gemm(const __half* __restrict__ Ah, const __half* __restrict__ Al,
        const __half* __restrict__ Wh, const __half* __restrict__ Wl,
        const float* __restrict__ bias,
        __half* __restrict__ Ch, __half* __restrict__ Cl,
        float* __restrict__ Cf, int M, int N, int K)
{
    extern __shared__ __half sm[];
    const int tid = threadIdx.x, wid = tid >> 5, lid = tid & 31;
    const int brow = blockIdx.y * TM, bcol = blockIdx.x * TN;
    const int m0 = (wid & 3) * 32;
    const int n0 = (wid >> 2) * 64;
    const uint32_t sbase = smem_u32(sm);

    auto load_stage = [&](int chunk, int slot) {
        const int kc = chunk * KC;
#pragma unroll
        for (int p = 0; p < 8; p++) {
            int idx = p * 256 + tid;
            int plane = idx >> 9, c = idx & 511, row = c >> 2, seg = c & 3;
            const __half* gsrc;
            if (plane == 0)      gsrc = Ah + (size_t)(brow + row) * K + kc + seg * 8;
            else if (plane == 1) gsrc = Al + (size_t)(brow + row) * K + kc + seg * 8;
            else if (plane == 2) gsrc = Wh + (size_t)(bcol + row) * K + kc + seg * 8;
            else                 gsrc = Wl + (size_t)(bcol + row) * K + kc + seg * 8;
            uint32_t dst = sbase +
                2u * (uint32_t)(slot * STAGE_HALFS + plane * PLANE + row * ROWPAD + seg * 8);
            cp_async16(dst, gsrc);
        }
    };

    float acc[2][8][4];
#pragma unroll
    for (int mt = 0; mt < 2; mt++)
#pragma unroll
        for (int nt = 0; nt < 8; nt++)
#pragma unroll
            for (int q = 0; q < 4; q++) acc[mt][nt][q] = 0.0f;

    const int nch = K / KC;
    load_stage(0, 0); CP_COMMIT();
    load_stage(1, 1); CP_COMMIT();
    load_stage(2, 2); CP_COMMIT();

    for (int i = 0; i < nch; i++) {
        const int slot = i % 3;
        CP_WAIT2();
        __syncthreads();
        const uint32_t aHi = sbase + 2u * (uint32_t)(slot * STAGE_HALFS);
        const uint32_t aLo = aHi + 2u * PLANE;
        const uint32_t bHi = aHi + 4u * PLANE;
        const uint32_t bLo = aHi + 6u * PLANE;

#pragma unroll
        for (int s = 0; s < 2; s++) {
            const int k0 = s * 16;
            uint32_t ah[2][4], al[2][4], bh[8][2], bl[8][2];
#pragma unroll
            for (int mt = 0; mt < 2; mt++) {
                uint32_t off = 2u * (uint32_t)((m0 + mt * 16 + (lid & 15)) * ROWPAD
                                               + k0 + ((lid >> 4) << 3));
                ldsm4(ah[mt], aHi + off);
                ldsm4(al[mt], aLo + off);
            }
#pragma unroll
            for (int g = 0; g < 4; g++) {
                uint32_t off = 2u * (uint32_t)((n0 + g * 16 + (lid & 15)) * ROWPAD
                                               + k0 + ((lid >> 4) << 3));
                uint32_t r[4];
                ldsm4(r, bHi + off);
                bh[g * 2][0] = r[0]; bh[g * 2][1] = r[2];
                bh[g * 2 + 1][0] = r[1]; bh[g * 2 + 1][1] = r[3];
                ldsm4(r, bLo + off);
                bl[g * 2][0] = r[0]; bl[g * 2][1] = r[2];
                bl[g * 2 + 1][0] = r[1]; bl[g * 2 + 1][1] = r[3];
            }
#pragma unroll
            for (int mt = 0; mt < 2; mt++)
#pragma unroll
                for (int nt = 0; nt < 8; nt++) {
                    mma16816(acc[mt][nt], ah[mt], bh[nt]);
                    mma16816(acc[mt][nt], ah[mt], bl[nt]);
                    mma16816(acc[mt][nt], al[mt], bh[nt]);
                }
        }
        __syncthreads();
        if (i + 3 < nch) load_stage(i + 3, slot);
        CP_COMMIT();
    }

#pragma unroll
    for (int mt = 0; mt < 2; mt++) {
#pragma unroll
        for (int nt = 0; nt < 8; nt++) {
            const int col = bcol + n0 + nt * 8 + 2 * (lid & 3);
            const float b0 = bias[col], b1 = bias[col + 1];
#pragma unroll
            for (int h = 0; h < 2; h++) {
                const int row = brow + m0 + mt * 16 + (lid >> 2) + h * 8;
                float v0 = fmaf(acc[mt][nt][h * 2 + 0], UNSCALE, b0);
                float v1 = fmaf(acc[mt][nt][h * 2 + 1], UNSCALE, b1);
                if (RELU) { v0 = fmaxf(v0, 0.0f); v1 = fmaxf(v1, 0.0f); }
                const size_t off = (size_t)row * N + col;
                if (WF) {
                    *(float2*)&Cf[off] = make_float2(v0, v1);
                }
                if (WS) {
                    float s0 = v0 * ASCALE, s1 = v1 * ASCALE;
                    __half2 hh = __floats2half2_rn(s0, s1);
                    __half2 ll = __floats2half2_rn(s0 - __low2float(hh),
                                                   s1 - __high2float(hh));
                    *(__half2*)&Ch[off] = hh;
                    *(__half2*)&Cl[off] = ll;
                }
            }
        }
    }
}

// ---------------------------------------------------------------------------
// VQ path (fp32; f32x2 mainloop, identical per-dot fma chain + compare order)
// ---------------------------------------------------------------------------
__global__ void rownorm512(const float* __restrict__ X, float* __restrict__ out, int rows)
{
    int warp = (blockIdx.x * blockDim.x + threadIdx.x) >> 5;
    int lane = threadIdx.x & 31;
    if (warp >= rows) return;
    const float* xp = X + (size_t)warp * 512;
    float s = 0.0f;
#pragma unroll
    for (int k = lane; k < 512; k += 32) { float v = xp[k]; s = fmaf(v, v, s); }
#pragma unroll
    for (int o = 16; o; o >>= 1) s += __shfl_xor_sync(0xffffffffu, s, o);
    if (lane == 0) out[warp] = s;
}

__global__ __launch_bounds__(256)
void vq_dist(const float* __restrict__ Z, const float* __restrict__ CB,
             const float* __restrict__ zn, const float* __restrict__ en,
             float* __restrict__ cand_d, int* __restrict__ cand_i)
{
    __shared__ float As[16][132];
    __shared__ float Ws[16][132];
    __shared__ float sd[128][17];
    __shared__ int   si[128][16];

    const int K = 512;
    const int tid  = threadIdx.x;
    const int brow = blockIdx.y * 128;
    const int bcol = blockIdx.x * 128;

    const int lr = tid >> 2;
    const int lk = (tid & 3) << 2;
    const float* Ap = Z  + (size_t)(brow + lr) * K + lk;
    const float* Wp = CB + (size_t)(bcol + lr) * K + lk;

    const int trow = (tid >> 4) << 3;
    const int tcol = (tid & 15) << 3;

    unsigned long long acc2[8][4];
#pragma unroll
    for (int i = 0; i < 8; i++)
#pragma unroll
        for (int j = 0; j < 4; j++) acc2[i][j] = 0ull;

    for (int k0 = 0; k0 < 512; k0 += 16) {
#pragma unroll
        for (int h = 0; h < 2; h++) {
            float4 a = *(const float4*)(Ap + (size_t)(h * 64) * K + k0);
            float4 w = *(const float4*)(Wp + (size_t)(h * 64) * K + k0);
            int r = lr + h * 64;
            As[lk + 0][r] = a.x; As[lk + 1][r] = a.y;
            As[lk + 2][r] = a.z; As[lk + 3][r] = a.w;
            Ws[lk + 0][r] = w.x; Ws[lk + 1][r] = w.y;
            Ws[lk + 2][r] = w.z; Ws[lk + 3][r] = w.w;
        }
        __syncthreads();
#pragma unroll
        for (int kk = 0; kk < 16; kk++) {
            float ra[8];
            unsigned long long rb2[4];
            *(float4*)(ra)     = *(const float4*)&As[kk][trow];
            *(float4*)(ra + 4) = *(const float4*)&As[kk][trow + 4];
            *(ulonglong2*)(rb2)     = *(const ulonglong2*)&Ws[kk][tcol];
            *(ulonglong2*)(rb2 + 2) = *(const ulonglong2*)&Ws[kk][tcol + 4];
#pragma unroll
            for (int i = 0; i < 8; i++) {
                unsigned long long ap = dup_f32x2(ra[i]);
#pragma unroll
                for (int j = 0; j < 4; j++)
                    fma_f32x2(acc2[i][j], ap, rb2[j]);
            }
        }
        __syncthreads();
    }

    const int tx = tid & 15;
#pragma unroll
    for (int i = 0; i < 8; i++) {
        int row = trow + i;
        float znv = zn[brow + row];
        float accv[8];
#pragma unroll
        for (int j = 0; j < 4; j++)
            unpack_f32x2(accv[2 * j], accv[2 * j + 1], acc2[i][j]);
        float best = CUDART_INF_F;
        int   bi   = 0;
#pragma unroll
        for (int j = 0; j < 8; j++) {          // ascending code index
            int code = bcol + tcol + j;
            float t = znv + en[code];
            float d = t - 2.0f * accv[j];
            if (d < best) { best = d; bi = code; }
        }
        sd[row][tx] = best;
        si[row][tx] = bi;
    }
    __syncthreads();

    if (tid < 128) {
        float best = sd[tid][0];
        int   bi   = si[tid][0];
#pragma unroll
        for (int c = 1; c < 16; c++) {
            float d = sd[tid][c];
            if (d < best) { best = d; bi = si[tid][c]; }
        }
        cand_d[(size_t)blockIdx.x * BATCH + brow + tid] = best;
        cand_i[(size_t)blockIdx.x * BATCH + brow + tid] = bi;
    }
}

__global__ void vq_argmin_final(const float* __restrict__ cand_d,
                                const int* __restrict__ cand_i,
                                int* __restrict__ idx,
                                float* __restrict__ out_idx)
{
    int row = blockIdx.x * blockDim.x + threadIdx.x;
    if (row >= BATCH) return;
    float best = cand_d[row];
    int   bi   = cand_i[row];
#pragma unroll
    for (int c = 1; c < 64; c++) {
        float d = cand_d[(size_t)c * BATCH + row];
        if (d < best) { best = d; bi = cand_i[(size_t)c * BATCH + row]; }
    }
    idx[row] = bi;
    out_idx[row] = (float)bi;
}

__global__ __launch_bounds__(128)
void vq_gather(const float* __restrict__ Z, const float* __restrict__ CB,
               const int* __restrict__ idx,
               __half* __restrict__ zsth, __half* __restrict__ zstl,
               float* __restrict__ lossPart)
{
    __shared__ float sh[128];
    int row = blockIdx.x;
    int tid = threadIdx.x;
    int code = idx[row];

    const float4 zv = ((const float4*)(Z  + (size_t)row  * 512))[tid];
    const float4 ev = ((const float4*)(CB + (size_t)code * 512))[tid];
    float4 st;
    float d0 = ev.x - zv.x; st.x = (zv.x + d0) * ASCALE;
    float d1 = ev.y - zv.y; st.y = (zv.y + d1) * ASCALE;
    float d2 = ev.z - zv.z; st.z = (zv.z + d2) * ASCALE;
    float d3 = ev.w - zv.w; st.w = (zv.w + d3) * ASCALE;

    __half2 h0 = __floats2half2_rn(st.x, st.y);
    __half2 h1 = __floats2half2_rn(st.z, st.w);
    __half2 l0 = __floats2half2_rn(st.x - __low2float(h0), st.y - __high2float(h0));
    __half2 l1 = __floats2half2_rn(st.z - __low2float(h1), st.w - __high2float(h1));
    ((__half2*)(zsth + (size_t)row * 512))[2 * tid]     = h0;
    ((__half2*)(zsth + (size_t)row * 512))[2 * tid + 1] = h1;
    ((__half2*)(zstl + (size_t)row * 512))[2 * tid]     = l0;
    ((__half2*)(zstl + (size_t)row * 512))[2 * tid + 1] = l1;

    float s = d0 * d0 + d1 * d1 + d2 * d2 + d3 * d3;
    sh[tid] = s;
    __syncthreads();
#pragma unroll
    for (int o = 64; o; o >>= 1) {
        if (tid < o) sh[tid] += sh[tid + o];
        __syncthreads();
    }
    if (tid == 0) lossPart[row] = sh[0];
}

__global__ void loss_final(const float* __restrict__ part, float* __restrict__ out)
{
    __shared__ float sh[256];
    int tid = threadIdx.x;
    float s = 0.0f;
    for (int i = tid; i < BATCH; i += 256) s += part[i];
    sh[tid] = s;
    __syncthreads();
#pragma unroll
    for (int o = 128; o; o >>= 1) {
        if (tid < o) sh[tid] += sh[tid + o];
        __syncthreads();
    }
    if (tid == 0) *out = 1.25f * (sh[0] / (float)(BATCH * 512));
}

// ---------------------------------------------------------------------------
// Launch
// ---------------------------------------------------------------------------
#define GETSYM(p, s) cudaGetSymbolAddress((void**)&(p), s)

static float *p_bufB, *p_bufC, *p_bufD, *p_bufZ;
static __half *p_zsth, *p_zstl, *p_g1h, *p_g1l, *p_g2h, *p_g2l, *p_g3h, *p_g3l;
static __half *p_v1h, *p_v1l, *p_v2h, *p_v2l, *p_v3h, *p_v3l, *p_v4h, *p_v4l;
static float *p_znorm, *p_enorm, *p_cand_d, *p_lossPart;
static int *p_cand_i, *p_idx;
static bool s_init = false;

static inline void split_launch(const float* src, __half* h, __half* l, size_t n, float s)
{
    int n4 = (int)(n / 4);
    split4<<<(n4 + 255) / 256, 256>>>((const float4*)src, (__half2*)h, (__half2*)l, n4, s);
}

extern "C" void kernel_launch(void* const* d_in, const int* in_sizes, int n_in,
                              void* d_out, int out_size)
{
    if (!s_init) {
        GETSYM(p_bufB, g_bufB); GETSYM(p_bufC, g_bufC);
        GETSYM(p_bufD, g_bufD); GETSYM(p_bufZ, g_bufZ);
        GETSYM(p_zsth, g_zsth); GETSYM(p_zstl, g_zstl);
        GETSYM(p_g1h, g_g1h); GETSYM(p_g1l, g_g1l);
        GETSYM(p_g2h, g_g2h); GETSYM(p_g2l, g_g2l);
        GETSYM(p_g3h, g_g3h); GETSYM(p_g3l, g_g3l);
        GETSYM(p_v1h, g_v1h); GETSYM(p_v1l, g_v1l);
        GETSYM(p_v2h, g_v2h); GETSYM(p_v2l, g_v2l);
        GETSYM(p_v3h, g_v3h); GETSYM(p_v3l, g_v3l);
        GETSYM(p_v4h, g_v4h); GETSYM(p_v4l, g_v4l);
        GETSYM(p_znorm, g_znorm); GETSYM(p_enorm, g_enorm);
        GETSYM(p_cand_d, g_cand_d); GETSYM(p_cand_i, g_cand_i);
        GETSYM(p_idx, g_idx); GETSYM(p_lossPart, g_lossPart);
        cudaFuncSetAttribute(tc_gemm<1, 1, 0>,
                             cudaFuncAttributeMaxDynamicSharedMemorySize, GEMM_SMEM);
        cudaFuncSetAttribute(tc_gemm<0, 0, 1>,
                             cudaFuncAttributeMaxDynamicSharedMemorySize, GEMM_SMEM);
        s_init = true;
    }

    const float* x   = (const float*)d_in[0];
    const float* ew1 = (const float*)d_in[1];
    const float* eb1 = (const float*)d_in[2];
    const float* ew2 = (const float*)d_in[3];
    const float* eb2 = (const float*)d_in[4];
    const float* ew3 = (const float*)d_in[5];
    const float* eb3 = (const float*)d_in[6];
    const float* ew4 = (const float*)d_in[7];
    const float* eb4 = (const float*)d_in[8];
    const float* cb  = (const float*)d_in[9];
    const float* dw1 = (const float*)d_in[10];
    const float* db1 = (const float*)d_in[11];
    const float* dw2 = (const float*)d_in[12];
    const float* db2 = (const float*)d_in[13];
    const float* dw3 = (const float*)d_in[14];
    const float* db3 = (const float*)d_in[15];
    const float* dw4 = (const float*)d_in[16];
    const float* db4 = (const float*)d_in[17];
    float* out = (float*)d_out;

    dim3 blk(256);

    // ---- decoder weight splits ----
    split_launch(dw1, p_v1h, p_v1l, (size_t)1024 * 512, WSCALE);
    split_launch(dw2, p_v2h, p_v2l, (size_t)2048 * 1024, WSCALE);
    split_launch(dw3, p_v3h, p_v3l, (size_t)4096 * 2048, WSCALE);
    split_launch(dw4, p_v4h, p_v4l, (size_t)4096 * 4096, WSCALE);

    // ---- encoder (fp32, f32x2 — bit-identical chain to R3/R12) ----
    sgemm_bias<true ><<<dim3(2048/128, BATCH/128), blk>>>(x,      ew1, eb1, p_bufB, BATCH, 2048, 4096);
    sgemm_bias<true ><<<dim3(1024/128, BATCH/128), blk>>>(p_bufB, ew2, eb2, p_bufC, BATCH, 1024, 2048);
    sgemm_bias<true ><<<dim3( 512/128, BATCH/128), blk>>>(p_bufC, ew3, eb3, p_bufD, BATCH,  512, 1024);
    sgemm_bias<false><<<dim3( 512/128, BATCH/128), blk>>>(p_bufD, ew4, eb4, p_bufZ, BATCH,  512,  512);

    // ---- VQ (fp32, f32x2 mainloop — bit-identical) ----
    rownorm512<<<(BATCH * 32 + 255) / 256, blk>>>(p_bufZ, p_znorm, BATCH);
    rownorm512<<<(NCODE * 32 + 255) / 256, blk>>>(cb, p_enorm, NCODE);
    vq_dist<<<dim3(NCODE / 128, BATCH / 128), blk>>>(p_bufZ, cb, p_znorm, p_enorm,
                                                     p_cand_d, p_cand_i);
    vq_argmin_final<<<BATCH / 256, blk>>>(p_cand_d, p_cand_i, p_idx, out + IDX_OFF);
    vq_gather<<<BATCH, 128>>>(p_bufZ, cb, p_idx, p_zsth, p_zstl, p_lossPart);
    loss_final<<<1, 256>>>(p_lossPart, out + LOSS_OFF);

    // ---- decoder (HMMA split-fp16, unchanged from R12) ----
    tc_gemm<1,1,0><<<dim3( 8, 64), 256, GEMM_SMEM>>>(p_zsth, p_zstl, p_v1h, p_v1l, db1,
                                                     p_g1h, p_g1l, nullptr, BATCH, 1024, 512);
    tc_gemm<1,1,0><<<dim3(16, 64), 256, GEMM_SMEM>>>(p_g1h, p_g1l, p_v2h, p_v2l, db2,
                                                     p_g2h, p_g2l, nullptr, BATCH, 2048, 1024);
    tc_gemm<1,1,0><<<dim3(32, 64), 256, GEMM_SMEM>>>(p_g2h, p_g2l, p_v3h, p_v3l, db3,
                                                     p_g3h, p_g3l, nullptr, BATCH, 4096, 2048);
    tc_gemm<0,0,1><<<dim3(32, 64), 256, GEMM_SMEM>>>(p_g3h, p_g3l, p_v4h, p_v4l, db4,
                                                     nullptr, nullptr, out, BATCH, 4096, 4096);
}

// round 14
// speedup vs baseline: 1.0251x; 1.0251x over previous
#include <cuda_runtime.h>
#include <cuda_fp16.h>
#include <math_constants.h>
#include <cstdint>

// ---------------------------------------------------------------------------
// Problem constants
// ---------------------------------------------------------------------------
#define BATCH     8192
#define NCODE     8192
#define PRED_ELEMS ((size_t)BATCH * 4096)
#define LOSS_OFF   PRED_ELEMS
#define IDX_OFF    (PRED_ELEMS + 1)

// Exact power-of-2 scales keeping fp16 'lo' residuals in normal range
#define WSCALE 1024.0f
#define ASCALE 32.0f
#define UNSCALE (1.0f / (WSCALE * ASCALE))

// ---------------------------------------------------------------------------
// Helpers
// ---------------------------------------------------------------------------
__device__ __forceinline__ uint32_t smem_u32(const void* p) {
    uint32_t a;
    asm("{ .reg .u64 t; cvta.to.shared.u64 t, %1; cvt.u32.u64 %0, t; }"
        : "=r"(a) : "l"(p));
    return a;
}
__device__ __forceinline__ void cp_async16(uint32_t dst, const void* src) {
    asm volatile("cp.async.cg.shared.global [%0], [%1], 16;" :: "r"(dst), "l"(src) : "memory");
}
#define CP_COMMIT() asm volatile("cp.async.commit_group;" ::: "memory")
#define CP_WAIT2()  asm volatile("cp.async.wait_group 2;" ::: "memory")

__device__ __forceinline__ void ldsm4(uint32_t* r, uint32_t addr) {
    asm volatile("ldmatrix.sync.aligned.m8n8.x4.shared.b16 {%0,%1,%2,%3}, [%4];"
                 : "=r"(r[0]), "=r"(r[1]), "=r"(r[2]), "=r"(r[3]) : "r"(addr));
}
__device__ __forceinline__ void mma16816(float* c, const uint32_t* a, const uint32_t* b) {
    asm volatile("mma.sync.aligned.m16n8k16.row.col.f32.f16.f16.f32 "
                 "{%0,%1,%2,%3}, {%4,%5,%6,%7}, {%8,%9}, {%0,%1,%2,%3};"
                 : "+f"(c[0]), "+f"(c[1]), "+f"(c[2]), "+f"(c[3])
                 : "r"(a[0]), "r"(a[1]), "r"(a[2]), "r"(a[3]), "r"(b[0]), "r"(b[1]));
}

// Packed dual-fp32 FMA (each half is an exact fp32 fma.rn — per-element
// accumulation chains remain bit-identical to scalar FFMA).
__device__ __forceinline__ void fma_f32x2(unsigned long long& c,
                                          unsigned long long a,
                                          unsigned long long b) {
    asm("fma.rn.f32x2 %0, %1, %2, %0;" : "+l"(c) : "l"(a), "l"(b));
}
__device__ __forceinline__ unsigned long long dup_f32x2(float x) {
    unsigned long long d;
    asm("mov.b64 %0, {%1, %1};" : "=l"(d) : "f"(x));
    return d;
}
__device__ __forceinline__ void unpack_f32x2(float& lo, float& hi,
                                             unsigned long long v) {
    asm("mov.b64 {%0, %1}, %2;" : "=f"(lo), "=f"(hi) : "l"(v));
}

// ---------------------------------------------------------------------------
// Scratch buffers
// ---------------------------------------------------------------------------
__device__ float g_bufB[(size_t)BATCH * 2048];
__device__ float g_bufC[(size_t)BATCH * 1024];
__device__ float g_bufD[(size_t)BATCH * 512];
__device__ float g_bufZ[(size_t)BATCH * 512];
__device__ __half g_zsth[4194304], g_zstl[4194304];
__device__ __half g_g1h[8388608],  g_g1l[8388608];
__device__ __half g_g2h[16777216], g_g2l[16777216];
__device__ __half g_g3h[33554432], g_g3l[33554432];
__device__ __half g_v1h[524288],   g_v1l[524288];
__device__ __half g_v2h[2097152],  g_v2l[2097152];
__device__ __half g_v3h[8388608],  g_v3l[8388608];
__device__ __half g_v4h[16777216], g_v4l[16777216];
__device__ float g_znorm[BATCH];
__device__ float g_enorm[NCODE];
__device__ float g_cand_d[64 * BATCH];
__device__ int   g_cand_i[64 * BATCH];
__device__ int   g_idx[BATCH];
__device__ float g_lossPart[BATCH];

// ---------------------------------------------------------------------------
// fp32 SGEMM, double-buffered + LDG-prefetch pipeline, f32x2 mainloop.
// Per-output-element fma chain (ascending k, single accumulator) is identical
// to R3/R12/R13 — z / indices / loss stay bit-identical.
// ---------------------------------------------------------------------------
#define STS_TILE(BUF, A0, A1, W0, W1)                                          \
    do {                                                                       \
        As[BUF][lk + 0][lr] = (A0).x; As[BUF][lk + 1][lr] = (A0).y;            \
        As[BUF][lk + 2][lr] = (A0).z; As[BUF][lk + 3][lr] = (A0).w;            \
        As[BUF][lk + 0][lr + 64] = (A1).x; As[BUF][lk + 1][lr + 64] = (A1).y;  \
        As[BUF][lk + 2][lr + 64] = (A1).z; As[BUF][lk + 3][lr + 64] = (A1).w;  \
        Ws[BUF][lk + 0][lr] = (W0).x; Ws[BUF][lk + 1][lr] = (W0).y;            \
        Ws[BUF][lk + 2][lr] = (W0).z; Ws[BUF][lk + 3][lr] = (W0).w;            \
        Ws[BUF][lk + 0][lr + 64] = (W1).x; Ws[BUF][lk + 1][lr + 64] = (W1).y;  \
        Ws[BUF][lk + 2][lr + 64] = (W1).z; Ws[BUF][lk + 3][lr + 64] = (W1).w;  \
    } while (0)

template <bool RELU>
__global__ __launch_bounds__(256, 2)
void sgemm_bias(const float* __restrict__ A, const float* __restrict__ W,
                const float* __restrict__ bias, float* __restrict__ C,
                int M, int N, int K)
{
    __shared__ float As[2][16][132];
    __shared__ float Ws[2][16][132];

    const int tid  = threadIdx.x;
    const int brow = blockIdx.y * 128;
    const int bcol = blockIdx.x * 128;

    const int lr = tid >> 2;          // 0..63
    const int lk = (tid & 3) << 2;    // 0,4,8,12
    const float* Ap = A + (size_t)(brow + lr) * K + lk;
    const float* Wp = W + (size_t)(bcol + lr) * K + lk;

    const int trow = (tid >> 4) << 3;
    const int tcol = (tid & 15) << 3;

    unsigned long long acc2[8][4];
#pragma unroll
    for (int i = 0; i < 8; i++)
#pragma unroll
        for (int j = 0; j < 4; j++) acc2[i][j] = 0ull;

    float4 a0, a1, w0, w1;
    a0 = *(const float4*)(Ap);
    a1 = *(const float4*)(Ap + (size_t)64 * K);
    w0 = *(const float4*)(Wp);
    w1 = *(const float4*)(Wp + (size_t)64 * K);
    STS_TILE(0, a0, a1, w0, w1);

    const int nk = K >> 4;
    for (int i = 0; i < nk; i++) {
        const int cur = i & 1, nxt = cur ^ 1;
        __syncthreads();
        if (i + 1 < nk) {
            const float* Ap2 = Ap + (i + 1) * 16;
            const float* Wp2 = Wp + (i + 1) * 16;
            a0 = *(const float4*)(Ap2);
            a1 = *(const float4*)(Ap2 + (size_t)64 * K);
            w0 = *(const float4*)(Wp2);
            w1 = *(const float4*)(Wp2 + (size_t)64 * K);
        }
#pragma unroll
        for (int kk = 0; kk < 16; kk++) {
            float ra[8];
            unsigned long long rb2[4];
            *(float4*)(ra)     = *(const float4*)&As[cur][kk][trow];
            *(float4*)(ra + 4) = *(const float4*)&As[cur][kk][trow + 4];
            *(ulonglong2*)(rb2)     = *(const ulonglong2*)&Ws[cur][kk][tcol];
            *(ulonglong2*)(rb2 + 2) = *(const ulonglong2*)&Ws[cur][kk][tcol + 4];
#pragma unroll
            for (int r8 = 0; r8 < 8; r8++) {
                unsigned long long ap = dup_f32x2(ra[r8]);
#pragma unroll
                for (int j = 0; j < 4; j++)
                    fma_f32x2(acc2[r8][j], ap, rb2[j]);
            }
        }
        if (i + 1 < nk) STS_TILE(nxt, a0, a1, w0, w1);
    }

#pragma unroll
    for (int i = 0; i < 8; i++) {
        int row = brow + trow + i;
        float accv[8];
#pragma unroll
        for (int j = 0; j < 4; j++)
            unpack_f32x2(accv[2 * j], accv[2 * j + 1], acc2[i][j]);
#pragma unroll
        for (int j = 0; j < 8; j += 4) {
            int col = bcol + tcol + j;
            float4 bv = *(const float4*)&bias[col];
            float4 v;
            v.x = accv[j + 0] + bv.x;
            v.y = accv[j + 1] + bv.y;
            v.z = accv[j + 2] + bv.z;
            v.w = accv[j + 3] + bv.w;
            if (RELU) {
                v.x = fmaxf(v.x, 0.0f); v.y = fmaxf(v.y, 0.0f);
                v.z = fmaxf(v.z, 0.0f); v.w = fmaxf(v.w, 0.0f);
            }
            *(float4*)&C[(size_t)row * N + col] = v;
        }
    }
}

// ---------------------------------------------------------------------------
// fp32 -> (fp16 hi, fp16 lo) split of (x * scale)
// ---------------------------------------------------------------------------
__global__ void split4(const float4* __restrict__ src, __half2* __restrict__ h,
                       __half2* __restrict__ l, int n4, float scale)
{
    int i = blockIdx.x * blockDim.x + threadIdx.x;
    if (i >= n4) return;
    float4 x = src[i];
    x.x *= scale; x.y *= scale; x.z *= scale; x.w *= scale;
    __half2 h0 = __floats2half2_rn(x.x, x.y);
    __half2 h1 = __floats2half2_rn(x.z, x.w);
    __half2 l0 = __floats2half2_rn(x.x - __low2float(h0), x.y - __high2float(h0));
    __half2 l1 = __floats2half2_rn(x.z - __low2float(h1), x.w - __high2float(h1));
    h[2 * i] = h0; h[2 * i + 1] = h1;
    l[2 * i] = l0; l[2 * i + 1] = l1;
}

// ---------------------------------------------------------------------------
// HMMA split-fp16 GEMM (decoder; unchanged from R12 passing run)
// ---------------------------------------------------------------------------
#define TM 128
#define TN 128
#define KC 32
#define ROWPAD 40
#define PLANE (TM * ROWPAD)
#define STAGE_HALFS (4 * PLANE)
#define GEMM_SMEM (3 * STAGE_HALFS * 2)

template <int RELU, int WS, int WF>
__global__ void __launch_bounds__(256)
tc_gemm(const __half* __restrict__ Ah, const __half* __restrict__ Al,
        const __half* __restrict__ Wh, const __half* __restrict__ Wl,
        const float* __restrict__ bias,
        __half* __restrict__ Ch, __half* __restrict__ Cl,
        float* __restrict__ Cf, int M, int N, int K)
{
    extern __shared__ __half sm[];
    const int tid = threadIdx.x, wid = tid >> 5, lid = tid & 31;
    const int brow = blockIdx.y * TM, bcol = blockIdx.x * TN;
    const int m0 = (wid & 3) * 32;
    const int n0 = (wid >> 2) * 64;
    const uint32_t sbase = smem_u32(sm);

    auto load_stage = [&](int chunk, int slot) {
        const int kc = chunk * KC;
#pragma unroll
        for (int p = 0; p < 8; p++) {
            int idx = p * 256 + tid;
            int plane = idx >> 9, c = idx & 511, row = c >> 2, seg = c & 3;
            const __half* gsrc;
            if (plane == 0)      gsrc = Ah + (size_t)(brow + row) * K + kc + seg * 8;
            else if (plane == 1) gsrc = Al + (size_t)(brow + row) * K + kc + seg * 8;
            else if (plane == 2) gsrc = Wh + (size_t)(bcol + row) * K + kc + seg * 8;
            else                 gsrc = Wl + (size_t)(bcol + row) * K + kc + seg * 8;
            uint32_t dst = sbase +
                2u * (uint32_t)(slot * STAGE_HALFS + plane * PLANE + row * ROWPAD + seg * 8);
            cp_async16(dst, gsrc);
        }
    };

    float acc[2][8][4];
#pragma unroll
    for (int mt = 0; mt < 2; mt++)
#pragma unroll
        for (int nt = 0; nt < 8; nt++)
#pragma unroll
            for (int q = 0; q < 4; q++) acc[mt][nt][q] = 0.0f;

    const int nch = K / KC;
    load_stage(0, 0); CP_COMMIT();
    load_stage(1, 1); CP_COMMIT();
    load_stage(2, 2); CP_COMMIT();

    for (int i = 0; i < nch; i++) {
        const int slot = i % 3;
        CP_WAIT2();
        __syncthreads();
        const uint32_t aHi = sbase + 2u * (uint32_t)(slot * STAGE_HALFS);
        const uint32_t aLo = aHi + 2u * PLANE;
        const uint32_t bHi = aHi + 4u * PLANE;
        const uint32_t bLo = aHi + 6u * PLANE;

#pragma unroll
        for (int s = 0; s < 2; s++) {
            const int k0 = s * 16;
            uint32_t ah[2][4], al[2][4], bh[8][2], bl[8][2];
#pragma unroll
            for (int mt = 0; mt < 2; mt++) {
                uint32_t off = 2u * (uint32_t)((m0 + mt * 16 + (lid & 15)) * ROWPAD
                                               + k0 + ((lid >> 4) << 3));
                ldsm4(ah[mt], aHi + off);
                ldsm4(al[mt], aLo + off);
            }
#pragma unroll
            for (int g = 0; g < 4; g++) {
                uint32_t off = 2u * (uint32_t)((n0 + g * 16 + (lid & 15)) * ROWPAD
                                               + k0 + ((lid >> 4) << 3));
                uint32_t r[4];
                ldsm4(r, bHi + off);
                bh[g * 2][0] = r[0]; bh[g * 2][1] = r[2];
                bh[g * 2 + 1][0] = r[1]; bh[g * 2 + 1][1] = r[3];
                ldsm4(r, bLo + off);
                bl[g * 2][0] = r[0]; bl[g * 2][1] = r[2];
                bl[g * 2 + 1][0] = r[1]; bl[g * 2 + 1][1] = r[3];
            }
#pragma unroll
            for (int mt = 0; mt < 2; mt++)
#pragma unroll
                for (int nt = 0; nt < 8; nt++) {
                    mma16816(acc[mt][nt], ah[mt], bh[nt]);
                    mma16816(acc[mt][nt], ah[mt], bl[nt]);
                    mma16816(acc[mt][nt], al[mt], bh[nt]);
                }
        }
        __syncthreads();
        if (i + 3 < nch) load_stage(i + 3, slot);
        CP_COMMIT();
    }

#pragma unroll
    for (int mt = 0; mt < 2; mt++) {
#pragma unroll
        for (int nt = 0; nt < 8; nt++) {
            const int col = bcol + n0 + nt * 8 + 2 * (lid & 3);
            const float b0 = bias[col], b1 = bias[col + 1];
#pragma unroll
            for (int h = 0; h < 2; h++) {
                const int row = brow + m0 + mt * 16 + (lid >> 2) + h * 8;
                float v0 = fmaf(acc[mt][nt][h * 2 + 0], UNSCALE, b0);
                float v1 = fmaf(acc[mt][nt][h * 2 + 1], UNSCALE, b1);
                if (RELU) { v0 = fmaxf(v0, 0.0f); v1 = fmaxf(v1, 0.0f); }
                const size_t off = (size_t)row * N + col;
                if (WF) {
                    *(float2*)&Cf[off] = make_float2(v0, v1);
                }
                if (WS) {
                    float s0 = v0 * ASCALE, s1 = v1 * ASCALE;
                    __half2 hh = __floats2half2_rn(s0, s1);
                    __half2 ll = __floats2half2_rn(s0 - __low2float(hh),
                                                   s1 - __high2float(hh));
                    *(__half2*)&Ch[off] = hh;
                    *(__half2*)&Cl[off] = ll;
                }
            }
        }
    }
}

// ---------------------------------------------------------------------------
// VQ path (fp32; pipelined mainloop, identical fma chain + compare order)
// ---------------------------------------------------------------------------
__global__ void rownorm512(const float* __restrict__ X, float* __restrict__ out, int rows)
{
    int warp = (blockIdx.x * blockDim.x + threadIdx.x) >> 5;
    int lane = threadIdx.x & 31;
    if (warp >= rows) return;
    const float* xp = X + (size_t)warp * 512;
    float s = 0.0f;
#pragma unroll
    for (int k = lane; k < 512; k += 32) { float v = xp[k]; s = fmaf(v, v, s); }
#pragma unroll
    for (int o = 16; o; o >>= 1) s += __shfl_xor_sync(0xffffffffu, s, o);
    if (lane == 0) out[warp] = s;
}

__global__ __launch_bounds__(256, 2)
void vq_dist(const float* __restrict__ Z, const float* __restrict__ CB,
             const float* __restrict__ zn, const float* __restrict__ en,
             float* __restrict__ cand_d, int* __restrict__ cand_i)
{
    __shared__ float As[2][16][132];
    __shared__ float Ws[2][16][132];
    // sd/si alias the (dead-after-mainloop) tile buffers
    float (*sd)[17] = reinterpret_cast<float(*)[17]>(&As[0][0][0]);
    int   (*si)[16] = reinterpret_cast<int(*)[16]>(&Ws[0][0][0]);

    const int K = 512;
    const int tid  = threadIdx.x;
    const int brow = blockIdx.y * 128;
    const int bcol = blockIdx.x * 128;

    const int lr = tid >> 2;
    const int lk = (tid & 3) << 2;
    const float* Ap = Z  + (size_t)(brow + lr) * K + lk;
    const float* Wp = CB + (size_t)(bcol + lr) * K + lk;

    const int trow = (tid >> 4) << 3;
    const int tcol = (tid & 15) << 3;

    unsigned long long acc2[8][4];
#pragma unroll
    for (int i = 0; i < 8; i++)
#pragma unroll
        for (int j = 0; j < 4; j++) acc2[i][j] = 0ull;

    float4 a0, a1, w0, w1;
    a0 = *(const float4*)(Ap);
    a1 = *(const float4*)(Ap + (size_t)64 * K);
    w0 = *(const float4*)(Wp);
    w1 = *(const float4*)(Wp + (size_t)64 * K);
    STS_TILE(0, a0, a1, w0, w1);

    const int nk = K >> 4;     // 32
    for (int i = 0; i < nk; i++) {
        const int cur = i & 1, nxt = cur ^ 1;
        __syncthreads();
        if (i + 1 < nk) {
            const float* Ap2 = Ap + (i + 1) * 16;
            const float* Wp2 = Wp + (i + 1) * 16;
            a0 = *(const float4*)(Ap2);
            a1 = *(const float4*)(Ap2 + (size_t)64 * K);
            w0 = *(const float4*)(Wp2);
            w1 = *(const float4*)(Wp2 + (size_t)64 * K);
        }
#pragma unroll
        for (int kk = 0; kk < 16; kk++) {
            float ra[8];
            unsigned long long rb2[4];
            *(float4*)(ra)     = *(const float4*)&As[cur][kk][trow];
            *(float4*)(ra + 4) = *(const float4*)&As[cur][kk][trow + 4];
            *(ulonglong2*)(rb2)     = *(const ulonglong2*)&Ws[cur][kk][tcol];
            *(ulonglong2*)(rb2 + 2) = *(const ulonglong2*)&Ws[cur][kk][tcol + 4];
#pragma unroll
            for (int r8 = 0; r8 < 8; r8++) {
                unsigned long long ap = dup_f32x2(ra[r8]);
#pragma unroll
                for (int j = 0; j < 4; j++)
                    fma_f32x2(acc2[r8][j], ap, rb2[j]);
            }
        }
        if (i + 1 < nk) STS_TILE(nxt, a0, a1, w0, w1);
    }
    __syncthreads();   // all mainloop reads done before sd/si overwrite tiles

    const int tx = tid & 15;
#pragma unroll
    for (int i = 0; i < 8; i++) {
        int row = trow + i;
        float znv = zn[brow + row];
        float accv[8];
#pragma unroll
        for (int j = 0; j < 4; j++)
            unpack_f32x2(accv[2 * j], accv[2 * j + 1], acc2[i][j]);
        float best = CUDART_INF_F;
        int   bi   = 0;
#pragma unroll
        for (int j = 0; j < 8; j++) {          // ascending code index
            int code = bcol + tcol + j;
            float t = znv + en[code];
            float d = t - 2.0f * accv[j];
            if (d < best) { best = d; bi = code; }
        }
        sd[row][tx] = best;
        si[row][tx] = bi;
    }
    __syncthreads();

    if (tid < 128) {
        float best = sd[tid][0];
        int   bi   = si[tid][0];
#pragma unroll
        for (int c = 1; c < 16; c++) {
            float d = sd[tid][c];
            if (d < best) { best = d; bi = si[tid][c]; }
        }
        cand_d[(size_t)blockIdx.x * BATCH + brow + tid] = best;
        cand_i[(size_t)blockIdx.x * BATCH + brow + tid] = bi;
    }
}

__global__ void vq_argmin_final(const float* __restrict__ cand_d,
                                const int* __restrict__ cand_i,
                                int* __restrict__ idx,
                                float* __restrict__ out_idx)
{
    int row = blockIdx.x * blockDim.x + threadIdx.x;
    if (row >= BATCH) return;
    float best = cand_d[row];
    int   bi   = cand_i[row];
#pragma unroll
    for (int c = 1; c < 64; c++) {
        float d = cand_d[(size_t)c * BATCH + row];
        if (d < best) { best = d; bi = cand_i[(size_t)c * BATCH + row]; }
    }
    idx[row] = bi;
    out_idx[row] = (float)bi;
}

__global__ __launch_bounds__(128)
void vq_gather(const float* __restrict__ Z, const float* __restrict__ CB,
               const int* __restrict__ idx,
               __half* __restrict__ zsth, __half* __restrict__ zstl,
               float* __restrict__ lossPart)
{
    __shared__ float sh[128];
    int row = blockIdx.x;
    int tid = threadIdx.x;
    int code = idx[row];

    const float4 zv = ((const float4*)(Z  + (size_t)row  * 512))[tid];
    const float4 ev = ((const float4*)(CB + (size_t)code * 512))[tid];
    float4 st;
    float d0 = ev.x - zv.x; st.x = (zv.x + d0) * ASCALE;
    float d1 = ev.y - zv.y; st.y = (zv.y + d1) * ASCALE;
    float d2 = ev.z - zv.z; st.z = (zv.z + d2) * ASCALE;
    float d3 = ev.w - zv.w; st.w = (zv.w + d3) * ASCALE;

    __half2 h0 = __floats2half2_rn(st.x, st.y);
    __half2 h1 = __floats2half2_rn(st.z, st.w);
    __half2 l0 = __floats2half2_rn(st.x - __low2float(h0), st.y - __high2float(h0));
    __half2 l1 = __floats2half2_rn(st.z - __low2float(h1), st.w - __high2float(h1));
    ((__half2*)(zsth + (size_t)row * 512))[2 * tid]     = h0;
    ((__half2*)(zsth + (size_t)row * 512))[2 * tid + 1] = h1;
    ((__half2*)(zstl + (size_t)row * 512))[2 * tid]     = l0;
    ((__half2*)(zstl + (size_t)row * 512))[2 * tid + 1] = l1;

    float s = d0 * d0 + d1 * d1 + d2 * d2 + d3 * d3;
    sh[tid] = s;
    __syncthreads();
#pragma unroll
    for (int o = 64; o; o >>= 1) {
        if (tid < o) sh[tid] += sh[tid + o];
        __syncthreads();
    }
    if (tid == 0) lossPart[row] = sh[0];
}

__global__ void loss_final(const float* __restrict__ part, float* __restrict__ out)
{
    __shared__ float sh[256];
    int tid = threadIdx.x;
    float s = 0.0f;
    for (int i = tid; i < BATCH; i += 256) s += part[i];
    sh[tid] = s;
    __syncthreads();
#pragma unroll
    for (int o = 128; o; o >>= 1) {
        if (tid < o) sh[tid] += sh[tid + o];
        __syncthreads();
    }
    if (tid == 0) *out = 1.25f * (sh[0] / (float)(BATCH * 512));
}

// ---------------------------------------------------------------------------
// Launch
// ---------------------------------------------------------------------------
#define GETSYM(p, s) cudaGetSymbolAddress((void**)&(p), s)

static float *p_bufB, *p_bufC, *p_bufD, *p_bufZ;
static __half *p_zsth, *p_zstl, *p_g1h, *p_g1l, *p_g2h, *p_g2l, *p_g3h, *p_g3l;
static __half *p_v1h, *p_v1l, *p_v2h, *p_v2l, *p_v3h, *p_v3l, *p_v4h, *p_v4l;
static float *p_znorm, *p_enorm, *p_cand_d, *p_lossPart;
static int *p_cand_i, *p_idx;
static bool s_init = false;

static inline void split_launch(const float* src, __half* h, __half* l, size_t n, float s)
{
    int n4 = (int)(n / 4);
    split4<<<(n4 + 255) / 256, 256>>>((const float4*)src, (__half2*)h, (__half2*)l, n4, s);
}

extern "C" void kernel_launch(void* const* d_in, const int* in_sizes, int n_in,
                              void* d_out, int out_size)
{
    if (!s_init) {
        GETSYM(p_bufB, g_bufB); GETSYM(p_bufC, g_bufC);
        GETSYM(p_bufD, g_bufD); GETSYM(p_bufZ, g_bufZ);
        GETSYM(p_zsth, g_zsth); GETSYM(p_zstl, g_zstl);
        GETSYM(p_g1h, g_g1h); GETSYM(p_g1l, g_g1l);
        GETSYM(p_g2h, g_g2h); GETSYM(p_g2l, g_g2l);
        GETSYM(p_g3h, g_g3h); GETSYM(p_g3l, g_g3l);
        GETSYM(p_v1h, g_v1h); GETSYM(p_v1l, g_v1l);
        GETSYM(p_v2h, g_v2h); GETSYM(p_v2l, g_v2l);
        GETSYM(p_v3h, g_v3h); GETSYM(p_v3l, g_v3l);
        GETSYM(p_v4h, g_v4h); GETSYM(p_v4l, g_v4l);
        GETSYM(p_znorm, g_znorm); GETSYM(p_enorm, g_enorm);
        GETSYM(p_cand_d, g_cand_d); GETSYM(p_cand_i, g_cand_i);
        GETSYM(p_idx, g_idx); GETSYM(p_lossPart, g_lossPart);
        cudaFuncSetAttribute(tc_gemm<1, 1, 0>,
                             cudaFuncAttributeMaxDynamicSharedMemorySize, GEMM_SMEM);
        cudaFuncSetAttribute(tc_gemm<0, 0, 1>,
                             cudaFuncAttributeMaxDynamicSharedMemorySize, GEMM_SMEM);
        s_init = true;
    }

    const float* x   = (const float*)d_in[0];
    const float* ew1 = (const float*)d_in[1];
    const float* eb1 = (const float*)d_in[2];
    const float* ew2 = (const float*)d_in[3];
    const float* eb2 = (const float*)d_in[4];
    const float* ew3 = (const float*)d_in[5];
    const float* eb3 = (const float*)d_in[6];
    const float* ew4 = (const float*)d_in[7];
    const float* eb4 = (const float*)d_in[8];
    const float* cb  = (const float*)d_in[9];
    const float* dw1 = (const float*)d_in[10];
    const float* db1 = (const float*)d_in[11];
    const float* dw2 = (const float*)d_in[12];
    const float* db2 = (const float*)d_in[13];
    const float* dw3 = (const float*)d_in[14];
    const float* db3 = (const float*)d_in[15];
    const float* dw4 = (const float*)d_in[16];
    const float* db4 = (const float*)d_in[17];
    float* out = (float*)d_out;

    dim3 blk(256);

    // ---- decoder weight splits ----
    split_launch(dw1, p_v1h, p_v1l, (size_t)1024 * 512, WSCALE);
    split_launch(dw2, p_v2h, p_v2l, (size_t)2048 * 1024, WSCALE);
    split_launch(dw3, p_v3h, p_v3l, (size_t)4096 * 2048, WSCALE);
    split_launch(dw4, p_v4h, p_v4l, (size_t)4096 * 4096, WSCALE);

    // ---- encoder (fp32, pipelined — bit-identical chain to R3/R12/R13) ----
    sgemm_bias<true ><<<dim3(2048/128, BATCH/128), blk>>>(x,      ew1, eb1, p_bufB, BATCH, 2048, 4096);
    sgemm_bias<true ><<<dim3(1024/128, BATCH/128), blk>>>(p_bufB, ew2, eb2, p_bufC, BATCH, 1024, 2048);
    sgemm_bias<true ><<<dim3( 512/128, BATCH/128), blk>>>(p_bufC, ew3, eb3, p_bufD, BATCH,  512, 1024);
    sgemm_bias<false><<<dim3( 512/128, BATCH/128), blk>>>(p_bufD, ew4, eb4, p_bufZ, BATCH,  512,  512);

    // ---- VQ (fp32, pipelined mainloop — bit-identical) ----
    rownorm512<<<(BATCH * 32 + 255) / 256, blk>>>(p_bufZ, p_znorm, BATCH);
    rownorm512<<<(NCODE * 32 + 255) / 256, blk>>>(cb, p_enorm, NCODE);
    vq_dist<<<dim3(NCODE / 128, BATCH / 128), blk>>>(p_bufZ, cb, p_znorm, p_enorm,
                                                     p_cand_d, p_cand_i);
    vq_argmin_final<<<BATCH / 256, blk>>>(p_cand_d, p_cand_i, p_idx, out + IDX_OFF);
    vq_gather<<<BATCH, 128>>>(p_bufZ, cb, p_idx, p_zsth, p_zstl, p_lossPart);
    loss_final<<<1, 256>>>(p_lossPart, out + LOSS_OFF);

    // ---- decoder (HMMA split-fp16, unchanged from R12) ----
    tc_gemm<1,1,0><<<dim3( 8, 64), 256, GEMM_SMEM>>>(p_zsth, p_zstl, p_v1h, p_v1l, db1,
                                                     p_g1h, p_g1l, nullptr, BATCH, 1024, 512);
    tc_gemm<1,1,0><<<dim3(16, 64), 256, GEMM_SMEM>>>(p_g1h, p_g1l, p_v2h, p_v2l, db2,
                                                     p_g2h, p_g2l, nullptr, BATCH, 2048, 1024);
    tc_gemm<1,1,0><<<dim3(32, 64), 256, GEMM_SMEM>>>(p_g2h, p_g2l, p_v3h, p_v3l, db3,
                                                     p_g3h, p_g3l, nullptr, BATCH, 4096, 2048);
    tc_gemm<0,0,1><<<dim3(32, 64), 256, GEMM_SMEM>>>(p_g3h, p_g3l, p_v4h, p_v4l, db4,
                                                     nullptr, nullptr, out, BATCH, 4096, 4096);
}

// round 15
// speedup vs baseline: 1.0925x; 1.0658x over previous
#include <cuda_runtime.h>
#include <cuda_fp16.h>
#include <math_constants.h>
#include <cstdint>

// ---------------------------------------------------------------------------
// Problem constants
// ---------------------------------------------------------------------------
#define BATCH     8192
#define NCODE     8192
#define PRED_ELEMS ((size_t)BATCH * 4096)
#define LOSS_OFF   PRED_ELEMS
#define IDX_OFF    (PRED_ELEMS + 1)

// Exact power-of-2 scales keeping fp16 'lo' residuals in normal range
#define WSCALE 1024.0f
#define ASCALE 32.0f
#define UNSCALE (1.0f / (WSCALE * ASCALE))

// ---------------------------------------------------------------------------
// Helpers
// ---------------------------------------------------------------------------
__device__ __forceinline__ uint32_t smem_u32(const void* p) {
    uint32_t a;
    asm("{ .reg .u64 t; cvta.to.shared.u64 t, %1; cvt.u32.u64 %0, t; }"
        : "=r"(a) : "l"(p));
    return a;
}
__device__ __forceinline__ void cp_async16(uint32_t dst, const void* src) {
    asm volatile("cp.async.cg.shared.global [%0], [%1], 16;" :: "r"(dst), "l"(src) : "memory");
}
#define CP_COMMIT() asm volatile("cp.async.commit_group;" ::: "memory")
#define CP_WAIT1()  asm volatile("cp.async.wait_group 1;" ::: "memory")

__device__ __forceinline__ void ldsm4(uint32_t* r, uint32_t addr) {
    asm volatile("ldmatrix.sync.aligned.m8n8.x4.shared.b16 {%0,%1,%2,%3}, [%4];"
                 : "=r"(r[0]), "=r"(r[1]), "=r"(r[2]), "=r"(r[3]) : "r"(addr));
}
__device__ __forceinline__ void mma16816(float* c, const uint32_t* a, const uint32_t* b) {
    asm volatile("mma.sync.aligned.m16n8k16.row.col.f32.f16.f16.f32 "
                 "{%0,%1,%2,%3}, {%4,%5,%6,%7}, {%8,%9}, {%0,%1,%2,%3};"
                 : "+f"(c[0]), "+f"(c[1]), "+f"(c[2]), "+f"(c[3])
                 : "r"(a[0]), "r"(a[1]), "r"(a[2]), "r"(a[3]), "r"(b[0]), "r"(b[1]));
}

// Packed dual-fp32 FMA (each half is an exact fp32 fma.rn — per-element
// accumulation chains remain bit-identical to scalar FFMA).
__device__ __forceinline__ void fma_f32x2(unsigned long long& c,
                                          unsigned long long a,
                                          unsigned long long b) {
    asm("fma.rn.f32x2 %0, %1, %2, %0;" : "+l"(c) : "l"(a), "l"(b));
}
__device__ __forceinline__ unsigned long long dup_f32x2(float x) {
    unsigned long long d;
    asm("mov.b64 %0, {%1, %1};" : "=l"(d) : "f"(x));
    return d;
}
__device__ __forceinline__ void unpack_f32x2(float& lo, float& hi,
                                             unsigned long long v) {
    asm("mov.b64 {%0, %1}, %2;" : "=f"(lo), "=f"(hi) : "l"(v));
}

// ---------------------------------------------------------------------------
// Scratch buffers
// ---------------------------------------------------------------------------
__device__ float g_bufB[(size_t)BATCH * 2048];
__device__ float g_bufC[(size_t)BATCH * 1024];
__device__ float g_bufD[(size_t)BATCH * 512];
__device__ float g_bufZ[(size_t)BATCH * 512];
__device__ __half g_zsth[4194304], g_zstl[4194304];
__device__ __half g_g1h[8388608],  g_g1l[8388608];
__device__ __half g_g2h[16777216], g_g2l[16777216];
__device__ __half g_g3h[33554432], g_g3l[33554432];
__device__ __half g_v1h[524288],   g_v1l[524288];
__device__ __half g_v2h[2097152],  g_v2l[2097152];
__device__ __half g_v3h[8388608],  g_v3l[8388608];
__device__ __half g_v4h[16777216], g_v4l[16777216];
__device__ float g_znorm[BATCH];
__device__ float g_enorm[NCODE];
__device__ float g_cand_d[64 * BATCH];
__device__ int   g_cand_i[64 * BATCH];
__device__ int   g_idx[BATCH];
__device__ float g_lossPart[BATCH];

// ---------------------------------------------------------------------------
// fp32 SGEMM, double-buffered + LDG-prefetch pipeline, f32x2 mainloop.
// FROZEN MATH: per-output-element fma chain (ascending k, single accumulator)
// must stay bit-identical to R3/R12/R13/R14 — z / indices / loss depend on it.
// ---------------------------------------------------------------------------
#define STS_TILE(BUF, A0, A1, W0, W1)                                          \
    do {                                                                       \
        As[BUF][lk + 0][lr] = (A0).x; As[BUF][lk + 1][lr] = (A0).y;            \
        As[BUF][lk + 2][lr] = (A0).z; As[BUF][lk + 3][lr] = (A0).w;            \
        As[BUF][lk + 0][lr + 64] = (A1).x; As[BUF][lk + 1][lr + 64] = (A1).y;  \
        As[BUF][lk + 2][lr + 64] = (A1).z; As[BUF][lk + 3][lr + 64] = (A1).w;  \
        Ws[BUF][lk + 0][lr] = (W0).x; Ws[BUF][lk + 1][lr] = (W0).y;            \
        Ws[BUF][lk + 2][lr] = (W0).z; Ws[BUF][lk + 3][lr] = (W0).w;            \
        Ws[BUF][lk + 0][lr + 64] = (W1).x; Ws[BUF][lk + 1][lr + 64] = (W1).y;  \
        Ws[BUF][lk + 2][lr + 64] = (W1).z; Ws[BUF][lk + 3][lr + 64] = (W1).w;  \
    } while (0)

template <bool RELU>
__global__ __launch_bounds__(256, 2)
void sgemm_bias(const float* __restrict__ A, const float* __restrict__ W,
                const float* __restrict__ bias, float* __restrict__ C,
                int M, int N, int K)
{
    __shared__ float As[2][16][132];
    __shared__ float Ws[2][16][132];

    const int tid  = threadIdx.x;
    const int brow = blockIdx.y * 128;
    const int bcol = blockIdx.x * 128;

    const int lr = tid >> 2;
    const int lk = (tid & 3) << 2;
    const float* Ap = A + (size_t)(brow + lr) * K + lk;
    const float* Wp = W + (size_t)(bcol + lr) * K + lk;

    const int trow = (tid >> 4) << 3;
    const int tcol = (tid & 15) << 3;

    unsigned long long acc2[8][4];
#pragma unroll
    for (int i = 0; i < 8; i++)
#pragma unroll
        for (int j = 0; j < 4; j++) acc2[i][j] = 0ull;

    float4 a0, a1, w0, w1;
    a0 = *(const float4*)(Ap);
    a1 = *(const float4*)(Ap + (size_t)64 * K);
    w0 = *(const float4*)(Wp);
    w1 = *(const float4*)(Wp + (size_t)64 * K);
    STS_TILE(0, a0, a1, w0, w1);

    const int nk = K >> 4;
    for (int i = 0; i < nk; i++) {
        const int cur = i & 1, nxt = cur ^ 1;
        __syncthreads();
        if (i + 1 < nk) {
            const float* Ap2 = Ap + (i + 1) * 16;
            const float* Wp2 = Wp + (i + 1) * 16;
            a0 = *(const float4*)(Ap2);
            a1 = *(const float4*)(Ap2 + (size_t)64 * K);
            w0 = *(const float4*)(Wp2);
            w1 = *(const float4*)(Wp2 + (size_t)64 * K);
        }
#pragma unroll
        for (int kk = 0; kk < 16; kk++) {
            float ra[8];
            unsigned long long rb2[4];
            *(float4*)(ra)     = *(const float4*)&As[cur][kk][trow];
            *(float4*)(ra + 4) = *(const float4*)&As[cur][kk][trow + 4];
            *(ulonglong2*)(rb2)     = *(const ulonglong2*)&Ws[cur][kk][tcol];
            *(ulonglong2*)(rb2 + 2) = *(const ulonglong2*)&Ws[cur][kk][tcol + 4];
#pragma unroll
            for (int r8 = 0; r8 < 8; r8++) {
                unsigned long long ap = dup_f32x2(ra[r8]);
#pragma unroll
                for (int j = 0; j < 4; j++)
                    fma_f32x2(acc2[r8][j], ap, rb2[j]);
            }
        }
        if (i + 1 < nk) STS_TILE(nxt, a0, a1, w0, w1);
    }

#pragma unroll
    for (int i = 0; i < 8; i++) {
        int row = brow + trow + i;
        float accv[8];
#pragma unroll
        for (int j = 0; j < 4; j++)
            unpack_f32x2(accv[2 * j], accv[2 * j + 1], acc2[i][j]);
#pragma unroll
        for (int j = 0; j < 8; j += 4) {
            int col = bcol + tcol + j;
            float4 bv = *(const float4*)&bias[col];
            float4 v;
            v.x = accv[j + 0] + bv.x;
            v.y = accv[j + 1] + bv.y;
            v.z = accv[j + 2] + bv.z;
            v.w = accv[j + 3] + bv.w;
            if (RELU) {
                v.x = fmaxf(v.x, 0.0f); v.y = fmaxf(v.y, 0.0f);
                v.z = fmaxf(v.z, 0.0f); v.w = fmaxf(v.w, 0.0f);
            }
            *(float4*)&C[(size_t)row * N + col] = v;
        }
    }
}

// ---------------------------------------------------------------------------
// fp32 -> (fp16 hi, fp16 lo) split of (x * scale)
// ---------------------------------------------------------------------------
__global__ void split4(const float4* __restrict__ src, __half2* __restrict__ h,
                       __half2* __restrict__ l, int n4, float scale)
{
    int i = blockIdx.x * blockDim.x + threadIdx.x;
    if (i >= n4) return;
    float4 x = src[i];
    x.x *= scale; x.y *= scale; x.z *= scale; x.w *= scale;
    __half2 h0 = __floats2half2_rn(x.x, x.y);
    __half2 h1 = __floats2half2_rn(x.z, x.w);
    __half2 l0 = __floats2half2_rn(x.x - __low2float(h0), x.y - __high2float(h0));
    __half2 l1 = __floats2half2_rn(x.z - __low2float(h1), x.w - __high2float(h1));
    h[2 * i] = h0; h[2 * i + 1] = h1;
    l[2 * i] = l0; l[2 * i + 1] = l1;
}

// ---------------------------------------------------------------------------
// HMMA split-fp16 GEMM v2 (decoder): CTA 128x128, 4 warps, warp tile 64x64,
// 2-stage cp.async, 2 CTAs/SM. 1.5x less LDSM traffic vs v1 (A and B both
// 2x-read); co-resident CTAs hide LDSM/MMA latency and barriers.
// ---------------------------------------------------------------------------
#define KC 32
#define ROWPAD 40
#define PLANE (128 * ROWPAD)             // 5120 halfs per plane
#define STAGE_HALFS (4 * PLANE)          // Ahi,Alo,Whi,Wlo = 20480 halfs
#define GEMM2_SMEM (2 * STAGE_HALFS * 2) // 81920 bytes

template <int RELU, int WS, int WF>
__global__ void __launch_bounds__(128, 2)
tc_gemm2(const __half* __restrict__ Ah, const __half* __restrict__ Al,
         const __half* __restrict__ Wh, const __half* __restrict__ Wl,
         const float* __restrict__ bias,
         __half* __restrict__ Ch, __half* __restrict__ Cl,
         float* __restrict__ Cf, int M, int N, int K)
{
    extern __shared__ __half sm[];
    const int tid = threadIdx.x, wid = tid >> 5, lid = tid & 31;
    const int brow = blockIdx.y * 128, bcol = blockIdx.x * 128;
    const int m0 = (wid & 1) * 64;      // warp m-offset (2 m-halves)
    const int n0 = (wid >> 1) * 64;     // warp n-offset (2 n-halves)
    const uint32_t sbase = smem_u32(sm);

    auto load_stage = [&](int chunk, int slot) {
        const int kc = chunk * KC;
#pragma unroll
        for (int p = 0; p < 16; p++) {
            int idx = p * 128 + tid;
            int plane = idx >> 9, c = idx & 511, row = c >> 2, seg = c & 3;
            const __half* gsrc;
            if (plane == 0)      gsrc = Ah + (size_t)(brow + row) * K + kc + seg * 8;
            else if (plane == 1) gsrc = Al + (size_t)(brow + row) * K + kc + seg * 8;
            else if (plane == 2) gsrc = Wh + (size_t)(bcol + row) * K + kc + seg * 8;
            else                 gsrc = Wl + (size_t)(bcol + row) * K + kc + seg * 8;
            uint32_t dst = sbase +
                2u * (uint32_t)(slot * STAGE_HALFS + plane * PLANE + row * ROWPAD + seg * 8);
            cp_async16(dst, gsrc);
        }
    };

    float acc[4][8][4];
#pragma unroll
    for (int mt = 0; mt < 4; mt++)
#pragma unroll
        for (int nt = 0; nt < 8; nt++)
#pragma unroll
            for (int q = 0; q < 4; q++) acc[mt][nt][q] = 0.0f;

    const int nch = K / KC;
    load_stage(0, 0); CP_COMMIT();
    load_stage(1, 1); CP_COMMIT();

    for (int i = 0; i < nch; i++) {
        const int slot = i & 1;
        CP_WAIT1();
        __syncthreads();
        const uint32_t aHi = sbase + 2u * (uint32_t)(slot * STAGE_HALFS);
        const uint32_t aLo = aHi + 2u * PLANE;
        const uint32_t bHi = aHi + 4u * PLANE;
        const uint32_t bLo = aHi + 6u * PLANE;

#pragma unroll
        for (int s = 0; s < 2; s++) {
            const int k0 = s * 16;
            uint32_t ah[4][4], al[4][4], bh[8][2], bl[8][2];
#pragma unroll
            for (int mt = 0; mt < 4; mt++) {
                uint32_t off = 2u * (uint32_t)((m0 + mt * 16 + (lid & 15)) * ROWPAD
                                               + k0 + ((lid >> 4) << 3));
                ldsm4(ah[mt], aHi + off);
                ldsm4(al[mt], aLo + off);
            }
#pragma unroll
            for (int g = 0; g < 4; g++) {
                uint32_t off = 2u * (uint32_t)((n0 + g * 16 + (lid & 15)) * ROWPAD
                                               + k0 + ((lid >> 4) << 3));
                uint32_t r[4];
                ldsm4(r, bHi + off);
                bh[g * 2][0] = r[0]; bh[g * 2][1] = r[2];
                bh[g * 2 + 1][0] = r[1]; bh[g * 2 + 1][1] = r[3];
                ldsm4(r, bLo + off);
                bl[g * 2][0] = r[0]; bl[g * 2][1] = r[2];
                bl[g * 2 + 1][0] = r[1]; bl[g * 2 + 1][1] = r[3];
            }
#pragma unroll
            for (int mt = 0; mt < 4; mt++)
#pragma unroll
                for (int nt = 0; nt < 8; nt++) {
                    mma16816(acc[mt][nt], ah[mt], bh[nt]);
                    mma16816(acc[mt][nt], ah[mt], bl[nt]);
                    mma16816(acc[mt][nt], al[mt], bh[nt]);
                }
        }
        __syncthreads();
        if (i + 2 < nch) load_stage(i + 2, slot);
        CP_COMMIT();
    }

    // Epilogue: unscale + bias + ReLU + (fp32 store | fused scaled fp16 split)
#pragma unroll
    for (int mt = 0; mt < 4; mt++) {
#pragma unroll
        for (int nt = 0; nt < 8; nt++) {
            const int col = bcol + n0 + nt * 8 + 2 * (lid & 3);
            const float b0 = bias[col], b1 = bias[col + 1];
#pragma unroll
            for (int h = 0; h < 2; h++) {
                const int row = brow + m0 + mt * 16 + (lid >> 2) + h * 8;
                float v0 = fmaf(acc[mt][nt][h * 2 + 0], UNSCALE, b0);
                float v1 = fmaf(acc[mt][nt][h * 2 + 1], UNSCALE, b1);
                if (RELU) { v0 = fmaxf(v0, 0.0f); v1 = fmaxf(v1, 0.0f); }
                const size_t off = (size_t)row * N + col;
                if (WF) {
                    *(float2*)&Cf[off] = make_float2(v0, v1);
                }
                if (WS) {
                    float s0 = v0 * ASCALE, s1 = v1 * ASCALE;
                    __half2 hh = __floats2half2_rn(s0, s1);
                    __half2 ll = __floats2half2_rn(s0 - __low2float(hh),
                                                   s1 - __high2float(hh));
                    *(__half2*)&Ch[off] = hh;
                    *(__half2*)&Cl[off] = ll;
                }
            }
        }
    }
}

// ---------------------------------------------------------------------------
// VQ path (fp32 — FROZEN, bit-exact chain)
// ---------------------------------------------------------------------------
__global__ void rownorm512(const float* __restrict__ X, float* __restrict__ out, int rows)
{
    int warp = (blockIdx.x * blockDim.x + threadIdx.x) >> 5;
    int lane = threadIdx.x & 31;
    if (warp >= rows) return;
    const float* xp = X + (size_t)warp * 512;
    float s = 0.0f;
#pragma unroll
    for (int k = lane; k < 512; k += 32) { float v = xp[k]; s = fmaf(v, v, s); }
#pragma unroll
    for (int o = 16; o; o >>= 1) s += __shfl_xor_sync(0xffffffffu, s, o);
    if (lane == 0) out[warp] = s;
}

__global__ __launch_bounds__(256, 2)
void vq_dist(const float* __restrict__ Z, const float* __restrict__ CB,
             const float* __restrict__ zn, const float* __restrict__ en,
             float* __restrict__ cand_d, int* __restrict__ cand_i)
{
    __shared__ float As[2][16][132];
    __shared__ float Ws[2][16][132];
    float (*sd)[17] = reinterpret_cast<float(*)[17]>(&As[0][0][0]);
    int   (*si)[16] = reinterpret_cast<int(*)[16]>(&Ws[0][0][0]);

    const int K = 512;
    const int tid  = threadIdx.x;
    const int brow = blockIdx.y * 128;
    const int bcol = blockIdx.x * 128;

    const int lr = tid >> 2;
    const int lk = (tid & 3) << 2;
    const float* Ap = Z  + (size_t)(brow + lr) * K + lk;
    const float* Wp = CB + (size_t)(bcol + lr) * K + lk;

    const int trow = (tid >> 4) << 3;
    const int tcol = (tid & 15) << 3;

    unsigned long long acc2[8][4];
#pragma unroll
    for (int i = 0; i < 8; i++)
#pragma unroll
        for (int j = 0; j < 4; j++) acc2[i][j] = 0ull;

    float4 a0, a1, w0, w1;
    a0 = *(const float4*)(Ap);
    a1 = *(const float4*)(Ap + (size_t)64 * K);
    w0 = *(const float4*)(Wp);
    w1 = *(const float4*)(Wp + (size_t)64 * K);
    STS_TILE(0, a0, a1, w0, w1);

    const int nk = K >> 4;
    for (int i = 0; i < nk; i++) {
        const int cur = i & 1, nxt = cur ^ 1;
        __syncthreads();
        if (i + 1 < nk) {
            const float* Ap2 = Ap + (i + 1) * 16;
            const float* Wp2 = Wp + (i + 1) * 16;
            a0 = *(const float4*)(Ap2);
            a1 = *(const float4*)(Ap2 + (size_t)64 * K);
            w0 = *(const float4*)(Wp2);
            w1 = *(const float4*)(Wp2 + (size_t)64 * K);
        }
#pragma unroll
        for (int kk = 0; kk < 16; kk++) {
            float ra[8];
            unsigned long long rb2[4];
            *(float4*)(ra)     = *(const float4*)&As[cur][kk][trow];
            *(float4*)(ra + 4) = *(const float4*)&As[cur][kk][trow + 4];
            *(ulonglong2*)(rb2)     = *(const ulonglong2*)&Ws[cur][kk][tcol];
            *(ulonglong2*)(rb2 + 2) = *(const ulonglong2*)&Ws[cur][kk][tcol + 4];
#pragma unroll
            for (int r8 = 0; r8 < 8; r8++) {
                unsigned long long ap = dup_f32x2(ra[r8]);
#pragma unroll
                for (int j = 0; j < 4; j++)
                    fma_f32x2(acc2[r8][j], ap, rb2[j]);
            }
        }
        if (i + 1 < nk) STS_TILE(nxt, a0, a1, w0, w1);
    }
    __syncthreads();

    const int tx = tid & 15;
#pragma unroll
    for (int i = 0; i < 8; i++) {
        int row = trow + i;
        float znv = zn[brow + row];
        float accv[8];
#pragma unroll
        for (int j = 0; j < 4; j++)
            unpack_f32x2(accv[2 * j], accv[2 * j + 1], acc2[i][j]);
        float best = CUDART_INF_F;
        int   bi   = 0;
#pragma unroll
        for (int j = 0; j < 8; j++) {
            int code = bcol + tcol + j;
            float t = znv + en[code];
            float d = t - 2.0f * accv[j];
            if (d < best) { best = d; bi = code; }
        }
        sd[row][tx] = best;
        si[row][tx] = bi;
    }
    __syncthreads();

    if (tid < 128) {
        float best = sd[tid][0];
        int   bi   = si[tid][0];
#pragma unroll
        for (int c = 1; c < 16; c++) {
            float d = sd[tid][c];
            if (d < best) { best = d; bi = si[tid][c]; }
        }
        cand_d[(size_t)blockIdx.x * BATCH + brow + tid] = best;
        cand_i[(size_t)blockIdx.x * BATCH + brow + tid] = bi;
    }
}

__global__ void vq_argmin_final(const float* __restrict__ cand_d,
                                const int* __restrict__ cand_i,
                                int* __restrict__ idx,
                                float* __restrict__ out_idx)
{
    int row = blockIdx.x * blockDim.x + threadIdx.x;
    if (row >= BATCH) return;
    float best = cand_d[row];
    int   bi   = cand_i[row];
#pragma unroll
    for (int c = 1; c < 64; c++) {
        float d = cand_d[(size_t)c * BATCH + row];
        if (d < best) { best = d; bi = cand_i[(size_t)c * BATCH + row]; }
    }
    idx[row] = bi;
    out_idx[row] = (float)bi;
}

__global__ __launch_bounds__(128)
void vq_gather(const float* __restrict__ Z, const float* __restrict__ CB,
               const int* __restrict__ idx,
               __half* __restrict__ zsth, __half* __restrict__ zstl,
               float* __restrict__ lossPart)
{
    __shared__ float sh[128];
    int row = blockIdx.x;
    int tid = threadIdx.x;
    int code = idx[row];

    const float4 zv = ((const float4*)(Z  + (size_t)row  * 512))[tid];
    const float4 ev = ((const float4*)(CB + (size_t)code * 512))[tid];
    float4 st;
    float d0 = ev.x - zv.x; st.x = (zv.x + d0) * ASCALE;
    float d1 = ev.y - zv.y; st.y = (zv.y + d1) * ASCALE;
    float d2 = ev.z - zv.z; st.z = (zv.z + d2) * ASCALE;
    float d3 = ev.w - zv.w; st.w = (zv.w + d3) * ASCALE;

    __half2 h0 = __floats2half2_rn(st.x, st.y);
    __half2 h1 = __floats2half2_rn(st.z, st.w);
    __half2 l0 = __floats2half2_rn(st.x - __low2float(h0), st.y - __high2float(h0));
    __half2 l1 = __floats2half2_rn(st.z - __low2float(h1), st.w - __high2float(h1));
    ((__half2*)(zsth + (size_t)row * 512))[2 * tid]     = h0;
    ((__half2*)(zsth + (size_t)row * 512))[2 * tid + 1] = h1;
    ((__half2*)(zstl + (size_t)row * 512))[2 * tid]     = l0;
    ((__half2*)(zstl + (size_t)row * 512))[2 * tid + 1] = l1;

    float s = d0 * d0 + d1 * d1 + d2 * d2 + d3 * d3;
    sh[tid] = s;
    __syncthreads();
#pragma unroll
    for (int o = 64; o; o >>= 1) {
        if (tid < o) sh[tid] += sh[tid + o];
        __syncthreads();
    }
    if (tid == 0) lossPart[row] = sh[0];
}

__global__ void loss_final(const float* __restrict__ part, float* __restrict__ out)
{
    __shared__ float sh[256];
    int tid = threadIdx.x;
    float s = 0.0f;
    for (int i = tid; i < BATCH; i += 256) s += part[i];
    sh[tid] = s;
    __syncthreads();
#pragma unroll
    for (int o = 128; o; o >>= 1) {
        if (tid < o) sh[tid] += sh[tid + o];
        __syncthreads();
    }
    if (tid == 0) *out = 1.25f * (sh[0] / (float)(BATCH * 512));
}

// ---------------------------------------------------------------------------
// Launch
// ---------------------------------------------------------------------------
#define GETSYM(p, s) cudaGetSymbolAddress((void**)&(p), s)

static float *p_bufB, *p_bufC, *p_bufD, *p_bufZ;
static __half *p_zsth, *p_zstl, *p_g1h, *p_g1l, *p_g2h, *p_g2l, *p_g3h, *p_g3l;
static __half *p_v1h, *p_v1l, *p_v2h, *p_v2l, *p_v3h, *p_v3l, *p_v4h, *p_v4l;
static float *p_znorm, *p_enorm, *p_cand_d, *p_lossPart;
static int *p_cand_i, *p_idx;
static bool s_init = false;

static inline void split_launch(const float* src, __half* h, __half* l, size_t n, float s)
{
    int n4 = (int)(n / 4);
    split4<<<(n4 + 255) / 256, 256>>>((const float4*)src, (__half2*)h, (__half2*)l, n4, s);
}

extern "C" void kernel_launch(void* const* d_in, const int* in_sizes, int n_in,
                              void* d_out, int out_size)
{
    if (!s_init) {
        GETSYM(p_bufB, g_bufB); GETSYM(p_bufC, g_bufC);
        GETSYM(p_bufD, g_bufD); GETSYM(p_bufZ, g_bufZ);
        GETSYM(p_zsth, g_zsth); GETSYM(p_zstl, g_zstl);
        GETSYM(p_g1h, g_g1h); GETSYM(p_g1l, g_g1l);
        GETSYM(p_g2h, g_g2h); GETSYM(p_g2l, g_g2l);
        GETSYM(p_g3h, g_g3h); GETSYM(p_g3l, g_g3l);
        GETSYM(p_v1h, g_v1h); GETSYM(p_v1l, g_v1l);
        GETSYM(p_v2h, g_v2h); GETSYM(p_v2l, g_v2l);
        GETSYM(p_v3h, g_v3h); GETSYM(p_v3l, g_v3l);
        GETSYM(p_v4h, g_v4h); GETSYM(p_v4l, g_v4l);
        GETSYM(p_znorm, g_znorm); GETSYM(p_enorm, g_enorm);
        GETSYM(p_cand_d, g_cand_d); GETSYM(p_cand_i, g_cand_i);
        GETSYM(p_idx, g_idx); GETSYM(p_lossPart, g_lossPart);
        cudaFuncSetAttribute(tc_gemm2<1, 1, 0>,
                             cudaFuncAttributeMaxDynamicSharedMemorySize, GEMM2_SMEM);
        cudaFuncSetAttribute(tc_gemm2<0, 0, 1>,
                             cudaFuncAttributeMaxDynamicSharedMemorySize, GEMM2_SMEM);
        s_init = true;
    }

    const float* x   = (const float*)d_in[0];
    const float* ew1 = (const float*)d_in[1];
    const float* eb1 = (const float*)d_in[2];
    const float* ew2 = (const float*)d_in[3];
    const float* eb2 = (const float*)d_in[4];
    const float* ew3 = (const float*)d_in[5];
    const float* eb3 = (const float*)d_in[6];
    const float* ew4 = (const float*)d_in[7];
    const float* eb4 = (const float*)d_in[8];
    const float* cb  = (const float*)d_in[9];
    const float* dw1 = (const float*)d_in[10];
    const float* db1 = (const float*)d_in[11];
    const float* dw2 = (const float*)d_in[12];
    const float* db2 = (const float*)d_in[13];
    const float* dw3 = (const float*)d_in[14];
    const float* db3 = (const float*)d_in[15];
    const float* dw4 = (const float*)d_in[16];
    const float* db4 = (const float*)d_in[17];
    float* out = (float*)d_out;

    dim3 blk(256);

    // ---- decoder weight splits ----
    split_launch(dw1, p_v1h, p_v1l, (size_t)1024 * 512, WSCALE);
    split_launch(dw2, p_v2h, p_v2l, (size_t)2048 * 1024, WSCALE);
    split_launch(dw3, p_v3h, p_v3l, (size_t)4096 * 2048, WSCALE);
    split_launch(dw4, p_v4h, p_v4l, (size_t)4096 * 4096, WSCALE);

    // ---- encoder (fp32, FROZEN bit-exact chain) ----
    sgemm_bias<true ><<<dim3(2048/128, BATCH/128), blk>>>(x,      ew1, eb1, p_bufB, BATCH, 2048, 4096);
    sgemm_bias<true ><<<dim3(1024/128, BATCH/128), blk>>>(p_bufB, ew2, eb2, p_bufC, BATCH, 1024, 2048);
    sgemm_bias<true ><<<dim3( 512/128, BATCH/128), blk>>>(p_bufC, ew3, eb3, p_bufD, BATCH,  512, 1024);
    sgemm_bias<false><<<dim3( 512/128, BATCH/128), blk>>>(p_bufD, ew4, eb4, p_bufZ, BATCH,  512,  512);

    // ---- VQ (fp32, FROZEN) ----
    rownorm512<<<(BATCH * 32 + 255) / 256, blk>>>(p_bufZ, p_znorm, BATCH);
    rownorm512<<<(NCODE * 32 + 255) / 256, blk>>>(cb, p_enorm, NCODE);
    vq_dist<<<dim3(NCODE / 128, BATCH / 128), blk>>>(p_bufZ, cb, p_znorm, p_enorm,
                                                     p_cand_d, p_cand_i);
    vq_argmin_final<<<BATCH / 256, blk>>>(p_cand_d, p_cand_i, p_idx, out + IDX_OFF);
    vq_gather<<<BATCH, 128>>>(p_bufZ, cb, p_idx, p_zsth, p_zstl, p_lossPart);
    loss_final<<<1, 256>>>(p_lossPart, out + LOSS_OFF);

    // ---- decoder (HMMA split-fp16 v2: 64x64 warp tiles, 2 CTAs/SM) ----
    tc_gemm2<1,1,0><<<dim3( 8, 64), 128, GEMM2_SMEM>>>(p_zsth, p_zstl, p_v1h, p_v1l, db1,
                                                       p_g1h, p_g1l, nullptr, BATCH, 1024, 512);
    tc_gemm2<1,1,0><<<dim3(16, 64), 128, GEMM2_SMEM>>>(p_g1h, p_g1l, p_v2h, p_v2l, db2,
                                                       p_g2h, p_g2l, nullptr, BATCH, 2048, 1024);
    tc_gemm2<1,1,0><<<dim3(32, 64), 128, GEMM2_SMEM>>>(p_g2h, p_g2l, p_v3h, p_v3l, db3,
                                                       p_g3h, p_g3l, nullptr, BATCH, 4096, 2048);
    tc_gemm2<0,0,1><<<dim3(32, 64), 128, GEMM2_SMEM>>>(p_g3h, p_g3l, p_v4h, p_v4l, db4,
                                                       nullptr, nullptr, out, BATCH, 4096, 4096);
}

// round 16
// speedup vs baseline: 1.0970x; 1.0041x over previous
#include <cuda_runtime.h>
#include <cuda_fp16.h>
#include <math_constants.h>
#include <cstdint>

// ---------------------------------------------------------------------------
// Problem constants
// ---------------------------------------------------------------------------
#define BATCH     8192
#define NCODE     8192
#define PRED_ELEMS ((size_t)BATCH * 4096)
#define LOSS_OFF   PRED_ELEMS
#define IDX_OFF    (PRED_ELEMS + 1)

#define WSCALE 1024.0f
#define ASCALE 32.0f
#define UNSCALE (1.0f / (WSCALE * ASCALE))

// ---------------------------------------------------------------------------
// Helpers
// ---------------------------------------------------------------------------
__device__ __forceinline__ uint32_t smem_u32(const void* p) {
    uint32_t a;
    asm("{ .reg .u64 t; cvta.to.shared.u64 t, %1; cvt.u32.u64 %0, t; }"
        : "=r"(a) : "l"(p));
    return a;
}
__device__ __forceinline__ void cp_async16(uint32_t dst, const void* src) {
    asm volatile("cp.async.cg.shared.global [%0], [%1], 16;" :: "r"(dst), "l"(src) : "memory");
}
#define CP_COMMIT() asm volatile("cp.async.commit_group;" ::: "memory")
#define CP_WAIT1()  asm volatile("cp.async.wait_group 1;" ::: "memory")

__device__ __forceinline__ void ldsm4(uint32_t* r, uint32_t addr) {
    asm volatile("ldmatrix.sync.aligned.m8n8.x4.shared.b16 {%0,%1,%2,%3}, [%4];"
                 : "=r"(r[0]), "=r"(r[1]), "=r"(r[2]), "=r"(r[3]) : "r"(addr));
}
__device__ __forceinline__ void mma16816(float* c, const uint32_t* a, const uint32_t* b) {
    asm volatile("mma.sync.aligned.m16n8k16.row.col.f32.f16.f16.f32 "
                 "{%0,%1,%2,%3}, {%4,%5,%6,%7}, {%8,%9}, {%0,%1,%2,%3};"
                 : "+f"(c[0]), "+f"(c[1]), "+f"(c[2]), "+f"(c[3])
                 : "r"(a[0]), "r"(a[1]), "r"(a[2]), "r"(a[3]), "r"(b[0]), "r"(b[1]));
}

// Packed dual-fp32 FMA (each half is an exact fp32 fma.rn — per-element
// accumulation chains remain bit-identical to scalar FFMA).
__device__ __forceinline__ void fma_f32x2(unsigned long long& c,
                                          unsigned long long a,
                                          unsigned long long b) {
    asm("fma.rn.f32x2 %0, %1, %2, %0;" : "+l"(c) : "l"(a), "l"(b));
}
__device__ __forceinline__ unsigned long long dup_f32x2(float x) {
    unsigned long long d;
    asm("mov.b64 %0, {%1, %1};" : "=l"(d) : "f"(x));
    return d;
}
__device__ __forceinline__ void unpack_f32x2(float& lo, float& hi,
                                             unsigned long long v) {
    asm("mov.b64 {%0, %1}, %2;" : "=f"(lo), "=f"(hi) : "l"(v));
}

// ---------------------------------------------------------------------------
// Scratch buffers
// ---------------------------------------------------------------------------
__device__ float g_bufB[(size_t)BATCH * 2048];
__device__ float g_bufC[(size_t)BATCH * 1024];
__device__ float g_bufD[(size_t)BATCH * 512];
__device__ float g_bufZ[(size_t)BATCH * 512];
__device__ __half g_zsth[4194304], g_zstl[4194304];
__device__ __half g_g1h[8388608],  g_g1l[8388608];
__device__ __half g_g2h[16777216], g_g2l[16777216];
__device__ __half g_g3h[33554432], g_g3l[33554432];
__device__ __half g_v1h[524288],   g_v1l[524288];
__device__ __half g_v2h[2097152],  g_v2l[2097152];
__device__ __half g_v3h[8388608],  g_v3l[8388608];
__device__ __half g_v4h[16777216], g_v4l[16777216];
__device__ float g_znorm[BATCH];
__device__ float g_enorm[NCODE];
__device__ float g_cand_d[64 * BATCH];
__device__ int   g_cand_i[64 * BATCH];
__device__ int   g_idx[BATCH];
__device__ float g_lossPart[BATCH];

// ---------------------------------------------------------------------------
// fp32 SGEMM v2: CTA 256(M)x128(N), 256 threads, thread tile 16x8,
// double-buffered smem + LDG prefetch, f32x2 FMAs.
// FROZEN MATH: per-output-element fma chain (ascending k, single fp32
// accumulator) is identical to R3..R15 — z / indices / loss bit-exact.
// A-tile smem reads are 16-lane broadcasts -> LDS crossbar no longer binds.
// ---------------------------------------------------------------------------
#define STS_TILE6(BUF)                                                         \
    do {                                                                       \
        As[BUF][lk + 0][lr]       = a0.x; As[BUF][lk + 1][lr]       = a0.y;    \
        As[BUF][lk + 2][lr]       = a0.z; As[BUF][lk + 3][lr]       = a0.w;    \
        As[BUF][lk + 0][lr + 64]  = a1.x; As[BUF][lk + 1][lr + 64]  = a1.y;    \
        As[BUF][lk + 2][lr + 64]  = a1.z; As[BUF][lk + 3][lr + 64]  = a1.w;    \
        As[BUF][lk + 0][lr + 128] = a2.x; As[BUF][lk + 1][lr + 128] = a2.y;    \
        As[BUF][lk + 2][lr + 128] = a2.z; As[BUF][lk + 3][lr + 128] = a2.w;    \
        As[BUF][lk + 0][lr + 192] = a3.x; As[BUF][lk + 1][lr + 192] = a3.y;    \
        As[BUF][lk + 2][lr + 192] = a3.z; As[BUF][lk + 3][lr + 192] = a3.w;    \
        Ws[BUF][lk + 0][lr]       = w0.x; Ws[BUF][lk + 1][lr]       = w0.y;    \
        Ws[BUF][lk + 2][lr]       = w0.z; Ws[BUF][lk + 3][lr]       = w0.w;    \
        Ws[BUF][lk + 0][lr + 64]  = w1.x; Ws[BUF][lk + 1][lr + 64]  = w1.y;    \
        Ws[BUF][lk + 2][lr + 64]  = w1.z; Ws[BUF][lk + 3][lr + 64]  = w1.w;    \
    } while (0)

#define LDG_TILE6(KOFF)                                                        \
    do {                                                                       \
        const float* Ap2 = Ap + (KOFF);                                        \
        const float* Wp2 = Wp + (KOFF);                                        \
        a0 = *(const float4*)(Ap2);                                            \
        a1 = *(const float4*)(Ap2 + (size_t)64 * K);                           \
        a2 = *(const float4*)(Ap2 + (size_t)128 * K);                          \
        a3 = *(const float4*)(Ap2 + (size_t)192 * K);                          \
        w0 = *(const float4*)(Wp2);                                            \
        w1 = *(const float4*)(Wp2 + (size_t)64 * K);                           \
    } while (0)

#define MAINLOOP_FMA(CUR)                                                      \
    do {                                                                       \
        _Pragma("unroll")                                                      \
        for (int kk = 0; kk < 16; kk++) {                                      \
            float ra[16];                                                      \
            unsigned long long rb2[4];                                         \
            *(float4*)(ra)      = *(const float4*)&As[CUR][kk][trow];          \
            *(float4*)(ra + 4)  = *(const float4*)&As[CUR][kk][trow + 4];      \
            *(float4*)(ra + 8)  = *(const float4*)&As[CUR][kk][trow + 8];      \
            *(float4*)(ra + 12) = *(const float4*)&As[CUR][kk][trow + 12];     \
            *(ulonglong2*)(rb2)     = *(const ulonglong2*)&Ws[CUR][kk][tcol];  \
            *(ulonglong2*)(rb2 + 2) = *(const ulonglong2*)&Ws[CUR][kk][tcol + 4]; \
            _Pragma("unroll")                                                  \
            for (int r16 = 0; r16 < 16; r16++) {                               \
                unsigned long long ap = dup_f32x2(ra[r16]);                    \
                _Pragma("unroll")                                              \
                for (int j = 0; j < 4; j++)                                    \
                    fma_f32x2(acc2[r16][j], ap, rb2[j]);                       \
            }                                                                  \
        }                                                                      \
    } while (0)

template <bool RELU>
__global__ __launch_bounds__(256, 1)
void sgemm_bias(const float* __restrict__ A, const float* __restrict__ W,
                const float* __restrict__ bias, float* __restrict__ C,
                int M, int N, int K)
{
    __shared__ float As[2][16][260];
    __shared__ float Ws[2][16][132];

    const int tid  = threadIdx.x;
    const int brow = blockIdx.y * 256;
    const int bcol = blockIdx.x * 128;

    const int lr = tid >> 2;          // 0..63
    const int lk = (tid & 3) << 2;    // 0,4,8,12
    const float* Ap = A + (size_t)(brow + lr) * K + lk;
    const float* Wp = W + (size_t)(bcol + lr) * K + lk;

    const int trow = (tid >> 4) << 4; // 0,16,...,240
    const int tcol = (tid & 15) << 3; // 0,8,...,120

    unsigned long long acc2[16][4];
#pragma unroll
    for (int i = 0; i < 16; i++)
#pragma unroll
        for (int j = 0; j < 4; j++) acc2[i][j] = 0ull;

    float4 a0, a1, a2, a3, w0, w1;
    LDG_TILE6(0);
    STS_TILE6(0);

    const int nk = K >> 4;
    for (int i = 0; i < nk; i++) {
        const int cur = i & 1, nxt = cur ^ 1;
        __syncthreads();
        if (i + 1 < nk) LDG_TILE6((i + 1) * 16);
        MAINLOOP_FMA(cur);
        if (i + 1 < nk) STS_TILE6(nxt);
    }

#pragma unroll
    for (int i = 0; i < 16; i++) {
        int row = brow + trow + i;
        float accv[8];
#pragma unroll
        for (int j = 0; j < 4; j++)
            unpack_f32x2(accv[2 * j], accv[2 * j + 1], acc2[i][j]);
#pragma unroll
        for (int j = 0; j < 8; j += 4) {
            int col = bcol + tcol + j;
            float4 bv = *(const float4*)&bias[col];
            float4 v;
            v.x = accv[j + 0] + bv.x;
            v.y = accv[j + 1] + bv.y;
            v.z = accv[j + 2] + bv.z;
            v.w = accv[j + 3] + bv.w;
            if (RELU) {
                v.x = fmaxf(v.x, 0.0f); v.y = fmaxf(v.y, 0.0f);
                v.z = fmaxf(v.z, 0.0f); v.w = fmaxf(v.w, 0.0f);
            }
            *(float4*)&C[(size_t)row * N + col] = v;
        }
    }
}

// ---------------------------------------------------------------------------
// fp32 -> (fp16 hi, fp16 lo) split of (x * scale)
// ---------------------------------------------------------------------------
__global__ void split4(const float4* __restrict__ src, __half2* __restrict__ h,
                       __half2* __restrict__ l, int n4, float scale)
{
    int i = blockIdx.x * blockDim.x + threadIdx.x;
    if (i >= n4) return;
    float4 x = src[i];
    x.x *= scale; x.y *= scale; x.z *= scale; x.w *= scale;
    __half2 h0 = __floats2half2_rn(x.x, x.y);
    __half2 h1 = __floats2half2_rn(x.z, x.w);
    __half2 l0 = __floats2half2_rn(x.x - __low2float(h0), x.y - __high2float(h0));
    __half2 l1 = __floats2half2_rn(x.z - __low2float(h1), x.w - __high2float(h1));
    h[2 * i] = h0; h[2 * i + 1] = h1;
    l[2 * i] = l0; l[2 * i + 1] = l1;
}

// ---------------------------------------------------------------------------
// HMMA split-fp16 GEMM v2 (decoder; unchanged from R15 passing run)
// ---------------------------------------------------------------------------
#define KC 32
#define ROWPAD 40
#define PLANE (128 * ROWPAD)
#define STAGE_HALFS (4 * PLANE)
#define GEMM2_SMEM (2 * STAGE_HALFS * 2)

template <int RELU, int WS, int WF>
__global__ void __launch_bounds__(128, 2)
tc_gemm2(const __half* __restrict__ Ah, const __half* __restrict__ Al,
         const __half* __restrict__ Wh, const __half* __restrict__ Wl,
         const float* __restrict__ bias,
         __half* __restrict__ Ch, __half* __restrict__ Cl,
         float* __restrict__ Cf, int M, int N, int K)
{
    extern __shared__ __half sm[];
    const int tid = threadIdx.x, wid = tid >> 5, lid = tid & 31;
    const int brow = blockIdx.y * 128, bcol = blockIdx.x * 128;
    const int m0 = (wid & 1) * 64;
    const int n0 = (wid >> 1) * 64;
    const uint32_t sbase = smem_u32(sm);

    auto load_stage = [&](int chunk, int slot) {
        const int kc = chunk * KC;
#pragma unroll
        for (int p = 0; p < 16; p++) {
            int idx = p * 128 + tid;
            int plane = idx >> 9, c = idx & 511, row = c >> 2, seg = c & 3;
            const __half* gsrc;
            if (plane == 0)      gsrc = Ah + (size_t)(brow + row) * K + kc + seg * 8;
            else if (plane == 1) gsrc = Al + (size_t)(brow + row) * K + kc + seg * 8;
            else if (plane == 2) gsrc = Wh + (size_t)(bcol + row) * K + kc + seg * 8;
            else                 gsrc = Wl + (size_t)(bcol + row) * K + kc + seg * 8;
            uint32_t dst = sbase +
                2u * (uint32_t)(slot * STAGE_HALFS + plane * PLANE + row * ROWPAD + seg * 8);
            cp_async16(dst, gsrc);
        }
    };

    float acc[4][8][4];
#pragma unroll
    for (int mt = 0; mt < 4; mt++)
#pragma unroll
        for (int nt = 0; nt < 8; nt++)
#pragma unroll
            for (int q = 0; q < 4; q++) acc[mt][nt][q] = 0.0f;

    const int nch = K / KC;
    load_stage(0, 0); CP_COMMIT();
    load_stage(1, 1); CP_COMMIT();

    for (int i = 0; i < nch; i++) {
        const int slot = i & 1;
        CP_WAIT1();
        __syncthreads();
        const uint32_t aHi = sbase + 2u * (uint32_t)(slot * STAGE_HALFS);
        const uint32_t aLo = aHi + 2u * PLANE;
        const uint32_t bHi = aHi + 4u * PLANE;
        const uint32_t bLo = aHi + 6u * PLANE;

#pragma unroll
        for (int s = 0; s < 2; s++) {
            const int k0 = s * 16;
            uint32_t ah[4][4], al[4][4], bh[8][2], bl[8][2];
#pragma unroll
            for (int mt = 0; mt < 4; mt++) {
                uint32_t off = 2u * (uint32_t)((m0 + mt * 16 + (lid & 15)) * ROWPAD
                                               + k0 + ((lid >> 4) << 3));
                ldsm4(ah[mt], aHi + off);
                ldsm4(al[mt], aLo + off);
            }
#pragma unroll
            for (int g = 0; g < 4; g++) {
                uint32_t off = 2u * (uint32_t)((n0 + g * 16 + (lid & 15)) * ROWPAD
                                               + k0 + ((lid >> 4) << 3));
                uint32_t r[4];
                ldsm4(r, bHi + off);
                bh[g * 2][0] = r[0]; bh[g * 2][1] = r[2];
                bh[g * 2 + 1][0] = r[1]; bh[g * 2 + 1][1] = r[3];
                ldsm4(r, bLo + off);
                bl[g * 2][0] = r[0]; bl[g * 2][1] = r[2];
                bl[g * 2 + 1][0] = r[1]; bl[g * 2 + 1][1] = r[3];
            }
#pragma unroll
            for (int mt = 0; mt < 4; mt++)
#pragma unroll
                for (int nt = 0; nt < 8; nt++) {
                    mma16816(acc[mt][nt], ah[mt], bh[nt]);
                    mma16816(acc[mt][nt], ah[mt], bl[nt]);
                    mma16816(acc[mt][nt], al[mt], bh[nt]);
                }
        }
        __syncthreads();
        if (i + 2 < nch) load_stage(i + 2, slot);
        CP_COMMIT();
    }

#pragma unroll
    for (int mt = 0; mt < 4; mt++) {
#pragma unroll
        for (int nt = 0; nt < 8; nt++) {
            const int col = bcol + n0 + nt * 8 + 2 * (lid & 3);
            const float b0 = bias[col], b1 = bias[col + 1];
#pragma unroll
            for (int h = 0; h < 2; h++) {
                const int row = brow + m0 + mt * 16 + (lid >> 2) + h * 8;
                float v0 = fmaf(acc[mt][nt][h * 2 + 0], UNSCALE, b0);
                float v1 = fmaf(acc[mt][nt][h * 2 + 1], UNSCALE, b1);
                if (RELU) { v0 = fmaxf(v0, 0.0f); v1 = fmaxf(v1, 0.0f); }
                const size_t off = (size_t)row * N + col;
                if (WF) {
                    *(float2*)&Cf[off] = make_float2(v0, v1);
                }
                if (WS) {
                    float s0 = v0 * ASCALE, s1 = v1 * ASCALE;
                    __half2 hh = __floats2half2_rn(s0, s1);
                    __half2 ll = __floats2half2_rn(s0 - __low2float(hh),
                                                   s1 - __high2float(hh));
                    *(__half2*)&Ch[off] = hh;
                    *(__half2*)&Cl[off] = ll;
                }
            }
        }
    }
}

// ---------------------------------------------------------------------------
// VQ path (fp32 — FROZEN chains; v2 geometry, ascending-order argmin)
// ---------------------------------------------------------------------------
__global__ void rownorm512(const float* __restrict__ X, float* __restrict__ out, int rows)
{
    int warp = (blockIdx.x * blockDim.x + threadIdx.x) >> 5;
    int lane = threadIdx.x & 31;
    if (warp >= rows) return;
    const float* xp = X + (size_t)warp * 512;
    float s = 0.0f;
#pragma unroll
    for (int k = lane; k < 512; k += 32) { float v = xp[k]; s = fmaf(v, v, s); }
#pragma unroll
    for (int o = 16; o; o >>= 1) s += __shfl_xor_sync(0xffffffffu, s, o);
    if (lane == 0) out[warp] = s;
}

__global__ __launch_bounds__(256, 1)
void vq_dist(const float* __restrict__ Z, const float* __restrict__ CB,
             const float* __restrict__ zn, const float* __restrict__ en,
             float* __restrict__ cand_d, int* __restrict__ cand_i)
{
    __shared__ float As[2][16][260];
    __shared__ float Ws[2][16][132];
    // sd/si alias the (dead-after-mainloop) tile buffers
    float (*sd)[17] = reinterpret_cast<float(*)[17]>(&As[0][0][0]);   // 256*17*4 <= 33280
    int   (*si)[16] = reinterpret_cast<int(*)[16]>(&Ws[0][0][0]);     // 256*16*4 <= 16896

    const int K = 512;
    const int tid  = threadIdx.x;
    const int brow = blockIdx.y * 256;
    const int bcol = blockIdx.x * 128;

    const int lr = tid >> 2;
    const int lk = (tid & 3) << 2;
    const float* Ap = Z  + (size_t)(brow + lr) * K + lk;
    const float* Wp = CB + (size_t)(bcol + lr) * K + lk;

    const int trow = (tid >> 4) << 4;
    const int tcol = (tid & 15) << 3;

    unsigned long long acc2[16][4];
#pragma unroll
    for (int i = 0; i < 16; i++)
#pragma unroll
        for (int j = 0; j < 4; j++) acc2[i][j] = 0ull;

    float4 a0, a1, a2, a3, w0, w1;
    LDG_TILE6(0);
    STS_TILE6(0);

    const int nk = K >> 4;     // 32
    for (int i = 0; i < nk; i++) {
        const int cur = i & 1, nxt = cur ^ 1;
        __syncthreads();
        if (i + 1 < nk) LDG_TILE6((i + 1) * 16);
        MAINLOOP_FMA(cur);
        if (i + 1 < nk) STS_TILE6(nxt);
    }
    __syncthreads();   // mainloop reads done before sd/si overwrite tiles

    const int tx = tid & 15;
#pragma unroll
    for (int i = 0; i < 16; i++) {
        int row = trow + i;
        float znv = zn[brow + row];
        float accv[8];
#pragma unroll
        for (int j = 0; j < 4; j++)
            unpack_f32x2(accv[2 * j], accv[2 * j + 1], acc2[i][j]);
        float best = CUDART_INF_F;
        int   bi   = 0;
#pragma unroll
        for (int j = 0; j < 8; j++) {          // ascending code index
            int code = bcol + tcol + j;
            float t = znv + en[code];
            float d = t - 2.0f * accv[j];
            if (d < best) { best = d; bi = code; }
        }
        sd[row][tx] = best;
        si[row][tx] = bi;
    }
    __syncthreads();

    {
        // one thread per row (256 rows), groups scanned in ascending code order
        float best = sd[tid][0];
        int   bi   = si[tid][0];
#pragma unroll
        for (int c = 1; c < 16; c++) {
            float d = sd[tid][c];
            if (d < best) { best = d; bi = si[tid][c]; }
        }
        cand_d[(size_t)blockIdx.x * BATCH + brow + tid] = best;
        cand_i[(size_t)blockIdx.x * BATCH + brow + tid] = bi;
    }
}

__global__ void vq_argmin_final(const float* __restrict__ cand_d,
                                const int* __restrict__ cand_i,
                                int* __restrict__ idx,
                                float* __restrict__ out_idx)
{
    int row = blockIdx.x * blockDim.x + threadIdx.x;
    if (row >= BATCH) return;
    float best = cand_d[row];
    int   bi   = cand_i[row];
#pragma unroll
    for (int c = 1; c < 64; c++) {
        float d = cand_d[(size_t)c * BATCH + row];
        if (d < best) { best = d; bi = cand_i[(size_t)c * BATCH + row]; }
    }
    idx[row] = bi;
    out_idx[row] = (float)bi;
}

__global__ __launch_bounds__(128)
void vq_gather(const float* __restrict__ Z, const float* __restrict__ CB,
               const int* __restrict__ idx,
               __half* __restrict__ zsth, __half* __restrict__ zstl,
               float* __restrict__ lossPart)
{
    __shared__ float sh[128];
    int row = blockIdx.x;
    int tid = threadIdx.x;
    int code = idx[row];

    const float4 zv = ((const float4*)(Z  + (size_t)row  * 512))[tid];
    const float4 ev = ((const float4*)(CB + (size_t)code * 512))[tid];
    float4 st;
    float d0 = ev.x - zv.x; st.x = (zv.x + d0) * ASCALE;
    float d1 = ev.y - zv.y; st.y = (zv.y + d1) * ASCALE;
    float d2 = ev.z - zv.z; st.z = (zv.z + d2) * ASCALE;
    float d3 = ev.w - zv.w; st.w = (zv.w + d3) * ASCALE;

    __half2 h0 = __floats2half2_rn(st.x, st.y);
    __half2 h1 = __floats2half2_rn(st.z, st.w);
    __half2 l0 = __floats2half2_rn(st.x - __low2float(h0), st.y - __high2float(h0));
    __half2 l1 = __floats2half2_rn(st.z - __low2float(h1), st.w - __high2float(h1));
    ((__half2*)(zsth + (size_t)row * 512))[2 * tid]     = h0;
    ((__half2*)(zsth + (size_t)row * 512))[2 * tid + 1] = h1;
    ((__half2*)(zstl + (size_t)row * 512))[2 * tid]     = l0;
    ((__half2*)(zstl + (size_t)row * 512))[2 * tid + 1] = l1;

    float s = d0 * d0 + d1 * d1 + d2 * d2 + d3 * d3;
    sh[tid] = s;
    __syncthreads();
#pragma unroll
    for (int o = 64; o; o >>= 1) {
        if (tid < o) sh[tid] += sh[tid + o];
        __syncthreads();
    }
    if (tid == 0) lossPart[row] = sh[0];
}

__global__ void loss_final(const float* __restrict__ part, float* __restrict__ out)
{
    __shared__ float sh[256];
    int tid = threadIdx.x;
    float s = 0.0f;
    for (int i = tid; i < BATCH; i += 256) s += part[i];
    sh[tid] = s;
    __syncthreads();
#pragma unroll
    for (int o = 128; o; o >>= 1) {
        if (tid < o) sh[tid] += sh[tid + o];
        __syncthreads();
    }
    if (tid == 0) *out = 1.25f * (sh[0] / (float)(BATCH * 512));
}

// ---------------------------------------------------------------------------
// Launch
// ---------------------------------------------------------------------------
#define GETSYM(p, s) cudaGetSymbolAddress((void**)&(p), s)

static float *p_bufB, *p_bufC, *p_bufD, *p_bufZ;
static __half *p_zsth, *p_zstl, *p_g1h, *p_g1l, *p_g2h, *p_g2l, *p_g3h, *p_g3l;
static __half *p_v1h, *p_v1l, *p_v2h, *p_v2l, *p_v3h, *p_v3l, *p_v4h, *p_v4l;
static float *p_znorm, *p_enorm, *p_cand_d, *p_lossPart;
static int *p_cand_i, *p_idx;
static bool s_init = false;

static inline void split_launch(const float* src, __half* h, __half* l, size_t n, float s)
{
    int n4 = (int)(n / 4);
    split4<<<(n4 + 255) / 256, 256>>>((const float4*)src, (__half2*)h, (__half2*)l, n4, s);
}

extern "C" void kernel_launch(void* const* d_in, const int* in_sizes, int n_in,
                              void* d_out, int out_size)
{
    if (!s_init) {
        GETSYM(p_bufB, g_bufB); GETSYM(p_bufC, g_bufC);
        GETSYM(p_bufD, g_bufD); GETSYM(p_bufZ, g_bufZ);
        GETSYM(p_zsth, g_zsth); GETSYM(p_zstl, g_zstl);
        GETSYM(p_g1h, g_g1h); GETSYM(p_g1l, g_g1l);
        GETSYM(p_g2h, g_g2h); GETSYM(p_g2l, g_g2l);
        GETSYM(p_g3h, g_g3h); GETSYM(p_g3l, g_g3l);
        GETSYM(p_v1h, g_v1h); GETSYM(p_v1l, g_v1l);
        GETSYM(p_v2h, g_v2h); GETSYM(p_v2l, g_v2l);
        GETSYM(p_v3h, g_v3h); GETSYM(p_v3l, g_v3l);
        GETSYM(p_v4h, g_v4h); GETSYM(p_v4l, g_v4l);
        GETSYM(p_znorm, g_znorm); GETSYM(p_enorm, g_enorm);
        GETSYM(p_cand_d, g_cand_d); GETSYM(p_cand_i, g_cand_i);
        GETSYM(p_idx, g_idx); GETSYM(p_lossPart, g_lossPart);
        cudaFuncSetAttribute(tc_gemm2<1, 1, 0>,
                             cudaFuncAttributeMaxDynamicSharedMemorySize, GEMM2_SMEM);
        cudaFuncSetAttribute(tc_gemm2<0, 0, 1>,
                             cudaFuncAttributeMaxDynamicSharedMemorySize, GEMM2_SMEM);
        s_init = true;
    }

    const float* x   = (const float*)d_in[0];
    const float* ew1 = (const float*)d_in[1];
    const float* eb1 = (const float*)d_in[2];
    const float* ew2 = (const float*)d_in[3];
    const float* eb2 = (const float*)d_in[4];
    const float* ew3 = (const float*)d_in[5];
    const float* eb3 = (const float*)d_in[6];
    const float* ew4 = (const float*)d_in[7];
    const float* eb4 = (const float*)d_in[8];
    const float* cb  = (const float*)d_in[9];
    const float* dw1 = (const float*)d_in[10];
    const float* db1 = (const float*)d_in[11];
    const float* dw2 = (const float*)d_in[12];
    const float* db2 = (const float*)d_in[13];
    const float* dw3 = (const float*)d_in[14];
    const float* db3 = (const float*)d_in[15];
    const float* dw4 = (const float*)d_in[16];
    const float* db4 = (const float*)d_in[17];
    float* out = (float*)d_out;

    dim3 blk(256);

    // ---- decoder weight splits ----
    split_launch(dw1, p_v1h, p_v1l, (size_t)1024 * 512, WSCALE);
    split_launch(dw2, p_v2h, p_v2l, (size_t)2048 * 1024, WSCALE);
    split_launch(dw3, p_v3h, p_v3l, (size_t)4096 * 2048, WSCALE);
    split_launch(dw4, p_v4h, p_v4l, (size_t)4096 * 4096, WSCALE);

    // ---- encoder (fp32 v2: 256x128 CTA, FROZEN bit-exact chains) ----
    sgemm_bias<true ><<<dim3(2048/128, BATCH/256), blk>>>(x,      ew1, eb1, p_bufB, BATCH, 2048, 4096);
    sgemm_bias<true ><<<dim3(1024/128, BATCH/256), blk>>>(p_bufB, ew2, eb2, p_bufC, BATCH, 1024, 2048);
    sgemm_bias<true ><<<dim3( 512/128, BATCH/256), blk>>>(p_bufC, ew3, eb3, p_bufD, BATCH,  512, 1024);
    sgemm_bias<false><<<dim3( 512/128, BATCH/256), blk>>>(p_bufD, ew4, eb4, p_bufZ, BATCH,  512,  512);

    // ---- VQ (fp32 v2 geometry, FROZEN chains) ----
    rownorm512<<<(BATCH * 32 + 255) / 256, blk>>>(p_bufZ, p_znorm, BATCH);
    rownorm512<<<(NCODE * 32 + 255) / 256, blk>>>(cb, p_enorm, NCODE);
    vq_dist<<<dim3(NCODE / 128, BATCH / 256), blk>>>(p_bufZ, cb, p_znorm, p_enorm,
                                                     p_cand_d, p_cand_i);
    vq_argmin_final<<<BATCH / 256, blk>>>(p_cand_d, p_cand_i, p_idx, out + IDX_OFF);
    vq_gather<<<BATCH, 128>>>(p_bufZ, cb, p_idx, p_zsth, p_zstl, p_lossPart);
    loss_final<<<1, 256>>>(p_lossPart, out + LOSS_OFF);

    // ---- decoder (HMMA split-fp16 v2, unchanged from R15) ----
    tc_gemm2<1,1,0><<<dim3( 8, 64), 128, GEMM2_SMEM>>>(p_zsth, p_zstl, p_v1h, p_v1l, db1,
                                                       p_g1h, p_g1l, nullptr, BATCH, 1024, 512);
    tc_gemm2<1,1,0><<<dim3(16, 64), 128, GEMM2_SMEM>>>(p_g1h, p_g1l, p_v2h, p_v2l, db2,
                                                       p_g2h, p_g2l, nullptr, BATCH, 2048, 1024);
    tc_gemm2<1,1,0><<<dim3(32, 64), 128, GEMM2_SMEM>>>(p_g2h, p_g2l, p_v3h, p_v3l, db3,
                                                       p_g3h, p_g3l, nullptr, BATCH, 4096, 2048);
    tc_gemm2<0,0,1><<<dim3(32, 64), 128, GEMM2_SMEM>>>(p_g3h, p_g3l, p_v4h, p_v4l, db4,
                                                       nullptr, nullptr, out, BATCH, 4096, 4096);
}